// round 1
// baseline (speedup 1.0000x reference)
#include <cuda_runtime.h>
#include <cuda_bf16.h>
#include <cstdint>

// Problem constants
#define EE 128          // E (rows / MSA depth)
#define LL 256          // L (sequence length)
#define HH 12           // heads
#define DHH 64          // head dim
#define DD 768          // D = H*DH
#define TD 2304         // 3*D
#define RR (EE*LL)      // 32768 rows

// ---------------- scratch (device globals; no allocation allowed) ----------
__device__ float g_xn  [(size_t)RR * DD];      // layernorm output        96 MB
__device__ float g_qkv [(size_t)RR * TD];      // qkv projection         288 MB
__device__ float g_x1  [(size_t)RR * DD];      // x + row_out             96 MB
__device__ float g_spart[(size_t)8 * HH * LL * LL]; // split-K partials   24 MB
__device__ float g_maps[(size_t)HH * LL * LL]; // row attention maps       3 MB
__device__ float g_rm  [HH * LL];              // row mask (sum over E)

// ---------------- LayerNorm: one CTA (256 thr) per row of 768 --------------
__global__ void ln_kernel(const float* __restrict__ xin, const float* __restrict__ g,
                          const float* __restrict__ b, float* __restrict__ y)
{
    int row = blockIdx.x, t = threadIdx.x;
    const float* xr = xin + (size_t)row * DD;
    float*       yr = y   + (size_t)row * DD;
    float v0 = xr[t], v1 = xr[t + 256], v2 = xr[t + 512];
    float s  = v0 + v1 + v2;
    float s2 = v0*v0 + v1*v1 + v2*v2;
    __shared__ float rs[8], rs2[8];
    #pragma unroll
    for (int o = 16; o > 0; o >>= 1) {
        s  += __shfl_xor_sync(0xffffffffu, s,  o);
        s2 += __shfl_xor_sync(0xffffffffu, s2, o);
    }
    if ((t & 31) == 0) { rs[t >> 5] = s; rs2[t >> 5] = s2; }
    __syncthreads();
    float ts = 0.f, ts2 = 0.f;
    #pragma unroll
    for (int w = 0; w < 8; w++) { ts += rs[w]; ts2 += rs2[w]; }
    float mu  = ts  * (1.0f / DD);
    float var = ts2 * (1.0f / DD) - mu * mu;
    float inv = rsqrtf(var + 1e-5f);
    yr[t]       = (v0 - mu) * inv * g[t]       + b[t];
    yr[t + 256] = (v1 - mu) * inv * g[t + 256] + b[t + 256];
    yr[t + 512] = (v2 - mu) * inv * g[t + 512] + b[t + 512];
}

// ---------------- QKV GEMM: C[R,2304] = A[R,768] * W[2304,768]^T + bias ----
// NT layout (both K-contiguous). 128x128x16 tile, 256 threads, 8x8/thread.
__global__ __launch_bounds__(256) void qkv_gemm(const float* __restrict__ A,
                                                const float* __restrict__ W,
                                                const float* __restrict__ bias,
                                                float* __restrict__ C)
{
    __shared__ float As[16][128];
    __shared__ float Bs[16][128];
    int n0 = blockIdx.x * 128;
    int m0 = blockIdx.y * 128;
    int tid = threadIdx.x;
    int ty = tid >> 4, tx = tid & 15;
    float acc[8][8] = {};
    int arow = tid >> 1;            // 0..127
    int ak4  = (tid & 1) * 2;       // 0 or 2
    const float* Aptr = A + (size_t)(m0 + arow) * DD;
    const float* Wptr = W + (size_t)(n0 + arow) * DD;

    for (int k0 = 0; k0 < DD; k0 += 16) {
        #pragma unroll
        for (int q = 0; q < 2; q++) {
            float4 a = *(const float4*)(Aptr + k0 + (ak4 + q) * 4);
            float4 w = *(const float4*)(Wptr + k0 + (ak4 + q) * 4);
            int kk = (ak4 + q) * 4;
            As[kk+0][arow]=a.x; As[kk+1][arow]=a.y; As[kk+2][arow]=a.z; As[kk+3][arow]=a.w;
            Bs[kk+0][arow]=w.x; Bs[kk+1][arow]=w.y; Bs[kk+2][arow]=w.z; Bs[kk+3][arow]=w.w;
        }
        __syncthreads();
        #pragma unroll
        for (int k = 0; k < 16; k++) {
            float a[8], b[8];
            *(float4*)(a)   = *(const float4*)&As[k][ty*8];
            *(float4*)(a+4) = *(const float4*)&As[k][ty*8+4];
            *(float4*)(b)   = *(const float4*)&Bs[k][tx*8];
            *(float4*)(b+4) = *(const float4*)&Bs[k][tx*8+4];
            #pragma unroll
            for (int u = 0; u < 8; u++)
                #pragma unroll
                for (int v = 0; v < 8; v++) acc[u][v] += a[u] * b[v];
        }
        __syncthreads();
    }
    #pragma unroll
    for (int u = 0; u < 8; u++) {
        int m = m0 + ty * 8 + u;
        float* Crow = C + (size_t)m * TD + n0 + tx * 8;
        #pragma unroll
        for (int v = 0; v < 8; v++) Crow[v] = acc[u][v] + bias[n0 + tx*8 + v];
    }
}

// ---------------- row mask: rm[h][l] = sum_e mask[h,e,l] -------------------
__global__ void rowmask_kernel(const float* __restrict__ mask, float* __restrict__ rm)
{
    int h = blockIdx.x, l = threadIdx.x;
    float s = 0.f;
    for (int e = 0; e < EE; e++) s += mask[((size_t)h * EE + e) * LL + l];
    rm[h * LL + l] = s;
}

// ---------------- row scores: S_h[i,j] = sum_{s,c} Q[s,i,h,c] K[s,j,h,c] ---
// split-K over s (8 splits of 16). 64x64 tile, 64 threads, 8x8/thread.
__global__ __launch_bounds__(64) void rowscore_kernel(const float* __restrict__ qkv,
                                                      float* __restrict__ spart)
{
    __shared__ float As[16][64];
    __shared__ float Bs[16][64];
    int h = blockIdx.z >> 3, ks = blockIdx.z & 7;
    int i0 = blockIdx.y * 64, j0 = blockIdx.x * 64;
    int t = threadIdx.x, ty = t >> 3, tx = t & 7;
    float acc[8][8] = {};

    for (int s = ks * 16; s < ks * 16 + 16; s++) {
        const float* qb = qkv + (size_t)(s * LL + i0 + t) * TD + h * DHH;
        const float* kb = qkv + (size_t)(s * LL + j0 + t) * TD + DD + h * DHH;
        for (int c0 = 0; c0 < DHH; c0 += 16) {
            #pragma unroll
            for (int q = 0; q < 4; q++) {
                float4 a = *(const float4*)(qb + c0 + q * 4);
                float4 b = *(const float4*)(kb + c0 + q * 4);
                As[q*4+0][t]=a.x; As[q*4+1][t]=a.y; As[q*4+2][t]=a.z; As[q*4+3][t]=a.w;
                Bs[q*4+0][t]=b.x; Bs[q*4+1][t]=b.y; Bs[q*4+2][t]=b.z; Bs[q*4+3][t]=b.w;
            }
            __syncthreads();
            #pragma unroll
            for (int k = 0; k < 16; k++) {
                float a[8], b[8];
                *(float4*)(a)   = *(const float4*)&As[k][ty*8];
                *(float4*)(a+4) = *(const float4*)&As[k][ty*8+4];
                *(float4*)(b)   = *(const float4*)&Bs[k][tx*8];
                *(float4*)(b+4) = *(const float4*)&Bs[k][tx*8+4];
                #pragma unroll
                for (int u = 0; u < 8; u++)
                    #pragma unroll
                    for (int v = 0; v < 8; v++) acc[u][v] += a[u] * b[v];
            }
            __syncthreads();
        }
    }
    float* outp = spart + (size_t)(ks * HH + h) * (LL * LL);
    #pragma unroll
    for (int u = 0; u < 8; u++) {
        float* orow = outp + (size_t)(i0 + ty*8 + u) * LL + j0 + tx*8;
        #pragma unroll
        for (int v = 0; v < 8; v++) orow[v] = acc[u][v];
    }
}

// ---------------- row softmax: reduce split-K partials + mask, softmax over j
__global__ void rowsoftmax_kernel(const float* __restrict__ spart,
                                  const float* __restrict__ rm,
                                  float* __restrict__ maps)
{
    int i = blockIdx.x, h = blockIdx.y, j = threadIdx.x;
    size_t idx = ((size_t)h * LL + i) * LL + j;
    float v = rm[h * LL + j];
    #pragma unroll
    for (int p = 0; p < 8; p++) v += spart[(size_t)p * (HH * (size_t)LL * LL) + idx];
    __shared__ float r1[8], r2[8];
    float m = v;
    #pragma unroll
    for (int o = 16; o > 0; o >>= 1) m = fmaxf(m, __shfl_xor_sync(0xffffffffu, m, o));
    if ((j & 31) == 0) r1[j >> 5] = m;
    __syncthreads();
    m = r1[0];
    #pragma unroll
    for (int w = 1; w < 8; w++) m = fmaxf(m, r1[w]);
    float e = __expf(v - m);
    float s = e;
    #pragma unroll
    for (int o = 16; o > 0; o >>= 1) s += __shfl_xor_sync(0xffffffffu, s, o);
    if ((j & 31) == 0) r2[j >> 5] = s;
    __syncthreads();
    s = 0.f;
    #pragma unroll
    for (int w = 0; w < 8; w++) s += r2[w];
    maps[idx] = e / s;
}

// ---------------- row out: x1 = x + maps_h @ V_h  (per h,s: 256x64x256) ----
// grid (itile=4, s=128, h=12), 64 threads, 64x64 tile, 8x8/thread.
__global__ __launch_bounds__(64) void rowout_kernel(const float* __restrict__ maps,
                                                    const float* __restrict__ qkv,
                                                    const float* __restrict__ xin,
                                                    float* __restrict__ xout)
{
    __shared__ float As[16][64];  // [j][i]
    __shared__ float Bs[16][64];  // [j][c]
    int h = blockIdx.z, s = blockIdx.y, i0 = blockIdx.x * 64;
    int t = threadIdx.x, ty = t >> 3, tx = t & 7;
    float acc[8][8] = {};
    const float* arow = maps + (size_t)(h * LL + i0 + t) * LL;

    for (int k0 = 0; k0 < LL; k0 += 16) {
        #pragma unroll
        for (int q = 0; q < 4; q++) {
            float4 a = *(const float4*)(arow + k0 + q * 4);
            As[q*4+0][t]=a.x; As[q*4+1][t]=a.y; As[q*4+2][t]=a.z; As[q*4+3][t]=a.w;
        }
        #pragma unroll
        for (int q = 0; q < 4; q++) {
            int f4 = t * 4 + q;          // 0..255
            int j  = f4 >> 4, c4 = f4 & 15;
            float4 b = *(const float4*)(qkv + (size_t)(s * LL + k0 + j) * TD
                                        + 2 * DD + h * DHH + c4 * 4);
            *(float4*)&Bs[j][c4 * 4] = b;
        }
        __syncthreads();
        #pragma unroll
        for (int k = 0; k < 16; k++) {
            float a[8], b[8];
            *(float4*)(a)   = *(const float4*)&As[k][ty*8];
            *(float4*)(a+4) = *(const float4*)&As[k][ty*8+4];
            *(float4*)(b)   = *(const float4*)&Bs[k][tx*8];
            *(float4*)(b+4) = *(const float4*)&Bs[k][tx*8+4];
            #pragma unroll
            for (int u = 0; u < 8; u++)
                #pragma unroll
                for (int v = 0; v < 8; v++) acc[u][v] += a[u] * b[v];
        }
        __syncthreads();
    }
    #pragma unroll
    for (int u = 0; u < 8; u++) {
        int i = i0 + ty * 8 + u;
        size_t base = (size_t)(s * LL + i) * DD + h * DHH + tx * 8;
        #pragma unroll
        for (int v2 = 0; v2 < 8; v2 += 4) {
            float4 xi = *(const float4*)(xin + base + v2);
            float4 o;
            o.x = xi.x + acc[u][v2+0]; o.y = xi.y + acc[u][v2+1];
            o.z = xi.z + acc[u][v2+2]; o.w = xi.w + acc[u][v2+3];
            *(float4*)(xout + base + v2) = o;
        }
    }
}

// ---------------- fused column attention: per (h,l) CTA --------------------
// S[i,j] = Q_i . K_j (+mask[h,j,l]); softmax over j; O = P V; out = x1 + O.
// Smem: QT/KT transposed [64][132] -> aliased by ST [128][132] after S-phase.
#define STQ 132
#define STV 68
#define COL_SMEM_BYTES ((128*STQ + 128*STV + 128) * 4)

__global__ __launch_bounds__(256) void colfused_kernel(const float* __restrict__ qkv,
                                                       const float* __restrict__ mask,
                                                       const float* __restrict__ xin,
                                                       float* __restrict__ out)
{
    extern __shared__ float cs[];
    float* QT = cs;                    // [64][STQ]  QT[c][i]
    float* KT = cs + 64 * STQ;         // [64][STQ]  KT[c][j]
    float* ST = cs;                    // [128][STQ] ST[j][i]  (aliases QT+KT)
    float* Vs = cs + 128 * STQ;        // [128][STV] Vs[j][c]
    float* mk = Vs + 128 * STV;        // [128]
    int l = blockIdx.x, h = blockIdx.y;
    int t = threadIdx.x;

    // Phase A: load Q,K (transposed), V, mask
    {
        int j = t >> 1, half = t & 1;
        const float* base = qkv + (size_t)(j * LL + l) * TD + h * DHH + half * 32;
        #pragma unroll
        for (int q = 0; q < 8; q++) {
            int c = half * 32 + q * 4;
            float4 qv = *(const float4*)(base + q * 4);
            float4 kv = *(const float4*)(base + DD + q * 4);
            float4 vv = *(const float4*)(base + 2 * DD + q * 4);
            QT[(c+0)*STQ + j] = qv.x; QT[(c+1)*STQ + j] = qv.y;
            QT[(c+2)*STQ + j] = qv.z; QT[(c+3)*STQ + j] = qv.w;
            KT[(c+0)*STQ + j] = kv.x; KT[(c+1)*STQ + j] = kv.y;
            KT[(c+2)*STQ + j] = kv.z; KT[(c+3)*STQ + j] = kv.w;
            *(float4*)&Vs[j * STV + c] = vv;
        }
        if (t < EE) mk[t] = mask[((size_t)h * EE + t) * LL + l];
    }
    __syncthreads();

    // Phase B: S = Q K^T  (128x128x64), 16x16 threads, 8x8/thread
    int ty = t >> 4, tx = t & 15;
    float accS[8][8] = {};
    #pragma unroll 4
    for (int c = 0; c < DHH; c++) {
        float a[8], b[8];
        *(float4*)(a)   = *(const float4*)&QT[c*STQ + ty*8];
        *(float4*)(a+4) = *(const float4*)&QT[c*STQ + ty*8+4];
        *(float4*)(b)   = *(const float4*)&KT[c*STQ + tx*8];
        *(float4*)(b+4) = *(const float4*)&KT[c*STQ + tx*8+4];
        #pragma unroll
        for (int u = 0; u < 8; u++)
            #pragma unroll
            for (int v = 0; v < 8; v++) accS[u][v] += a[u] * b[v];
    }
    __syncthreads();   // all QT/KT reads done before overwrite
    #pragma unroll
    for (int u = 0; u < 8; u++)
        #pragma unroll
        for (int v = 0; v < 8; v++)
            ST[(tx*8 + v) * STQ + (ty*8 + u)] = accS[u][v];
    __syncthreads();

    // Phase C: softmax over j (2 threads per i, 64 j's each)
    {
        int i = t >> 1, half = t & 1;
        float m = -1e30f;
        for (int tt = 0; tt < 64; tt++) {
            int j = half * 64 + tt;
            m = fmaxf(m, ST[j*STQ + i] + mk[j]);
        }
        m = fmaxf(m, __shfl_xor_sync(0xffffffffu, m, 1));
        float ssum = 0.f;
        for (int tt = 0; tt < 64; tt++) {
            int j = half * 64 + tt;
            float e = __expf(ST[j*STQ + i] + mk[j] - m);
            ST[j*STQ + i] = e;
            ssum += e;
        }
        ssum += __shfl_xor_sync(0xffffffffu, ssum, 1);
        float inv = 1.f / ssum;
        for (int tt = 0; tt < 64; tt++) {
            int j = half * 64 + tt;
            ST[j*STQ + i] *= inv;
        }
    }
    __syncthreads();

    // Phase D: O = P V  (128x64x128), 16x16 threads, 8x4/thread; residual out
    {
        int ti = t >> 4, tc = t & 15;
        float accO[8][4] = {};
        for (int j = 0; j < EE; j++) {
            float p[8];
            *(float4*)(p)   = *(const float4*)&ST[j*STQ + ti*8];
            *(float4*)(p+4) = *(const float4*)&ST[j*STQ + ti*8+4];
            float4 vv = *(const float4*)&Vs[j*STV + tc*4];
            #pragma unroll
            for (int u = 0; u < 8; u++) {
                accO[u][0] += p[u] * vv.x; accO[u][1] += p[u] * vv.y;
                accO[u][2] += p[u] * vv.z; accO[u][3] += p[u] * vv.w;
            }
        }
        #pragma unroll
        for (int u = 0; u < 8; u++) {
            int i = ti * 8 + u;
            size_t base = (size_t)(i * LL + l) * DD + h * DHH + tc * 4;
            float4 xi = *(const float4*)(xin + base);
            float4 o;
            o.x = xi.x + accO[u][0]; o.y = xi.y + accO[u][1];
            o.z = xi.z + accO[u][2]; o.w = xi.w + accO[u][3];
            *(float4*)(out + base) = o;
        }
    }
}

// ---------------- launch ---------------------------------------------------
extern "C" void kernel_launch(void* const* d_in, const int* in_sizes, int n_in,
                              void* d_out, int out_size)
{
    const float* x     = (const float*)d_in[0];
    const float* mask  = (const float*)d_in[1];
    const float* w_row = (const float*)d_in[2];
    const float* b_row = (const float*)d_in[3];
    const float* w_col = (const float*)d_in[4];
    const float* b_col = (const float*)d_in[5];
    const float* g1    = (const float*)d_in[6];
    const float* be1   = (const float*)d_in[7];
    const float* g2    = (const float*)d_in[8];
    const float* be2   = (const float*)d_in[9];
    float* out = (float*)d_out;

    float *p_xn, *p_qkv, *p_x1, *p_spart, *p_maps, *p_rm;
    cudaGetSymbolAddress((void**)&p_xn,    g_xn);
    cudaGetSymbolAddress((void**)&p_qkv,   g_qkv);
    cudaGetSymbolAddress((void**)&p_x1,    g_x1);
    cudaGetSymbolAddress((void**)&p_spart, g_spart);
    cudaGetSymbolAddress((void**)&p_maps,  g_maps);
    cudaGetSymbolAddress((void**)&p_rm,    g_rm);

    // ---- row attention ----
    ln_kernel<<<RR, 256>>>(x, g1, be1, p_xn);
    qkv_gemm<<<dim3(TD / 128, RR / 128), 256>>>(p_xn, w_row, b_row, p_qkv);
    rowmask_kernel<<<HH, LL>>>(mask, p_rm);
    rowscore_kernel<<<dim3(4, 4, HH * 8), 64>>>(p_qkv, p_spart);
    rowsoftmax_kernel<<<dim3(LL, HH), LL>>>(p_spart, p_rm, p_maps);
    rowout_kernel<<<dim3(4, EE, HH), 64>>>(p_maps, p_qkv, x, p_x1);

    // ---- column attention ----
    ln_kernel<<<RR, 256>>>(p_x1, g2, be2, p_xn);
    qkv_gemm<<<dim3(TD / 128, RR / 128), 256>>>(p_xn, w_col, b_col, p_qkv);
    cudaFuncSetAttribute(colfused_kernel,
                         cudaFuncAttributeMaxDynamicSharedMemorySize, COL_SMEM_BYTES);
    colfused_kernel<<<dim3(LL, HH), 256, COL_SMEM_BYTES>>>(p_qkv, mask, p_x1, out);
}

// round 6
// speedup vs baseline: 1.4208x; 1.4208x over previous
#include <cuda_runtime.h>
#include <cuda_bf16.h>
#include <cstdint>

// Problem constants
#define EE 128          // E (rows / MSA depth)
#define LL 256          // L (sequence length)
#define HH 12           // heads
#define DHH 64          // head dim
#define DD 768          // D = H*DH
#define TD 2304         // 3*D
#define RR (EE*LL)      // 32768 rows

// ---------------- scratch (device globals; no allocation allowed) ----------
__device__ __align__(256) float g_xn  [(size_t)RR * DD];           // layernorm output
__device__ __align__(256) float g_qkv [(size_t)RR * TD];           // qkv projection
__device__ __align__(256) float g_x1  [(size_t)RR * DD];           // x + row_out
__device__ __align__(256) float g_spart[(size_t)8 * HH * LL * LL]; // split-K partials
__device__ __align__(256) float g_maps[(size_t)HH * LL * LL];      // row attention maps
__device__ __align__(256) float g_rm  [HH * LL];                   // row mask

// ============================ helpers ======================================
__device__ __forceinline__ uint32_t smem_u32(const void* p) {
    uint32_t a;
    asm("{ .reg .u64 t; cvta.to.shared.u64 t, %1; cvt.u32.u64 %0, t; }"
        : "=r"(a) : "l"(p));
    return a;
}
__device__ __forceinline__ void cp_async16(uint32_t dst, const void* src) {
    asm volatile("cp.async.cg.shared.global [%0], [%1], 16;\n"
                 :: "r"(dst), "l"(src) : "memory");
}
#define CP_COMMIT() asm volatile("cp.async.commit_group;" ::: "memory")
#define CP_WAIT1()  asm volatile("cp.async.wait_group 1;" ::: "memory")

// split fp32 -> tf32 hi + tf32 lo (3xTF32 trick)
__device__ __forceinline__ void f32_split(float x, uint32_t& hi, uint32_t& lo) {
    uint32_t h;
    asm("cvt.rna.tf32.f32 %0, %1;" : "=r"(h) : "f"(x));
    float r = x - __uint_as_float(h);
    uint32_t l;
    asm("cvt.rna.tf32.f32 %0, %1;" : "=r"(l) : "f"(r));
    hi = h; lo = l;
}

__device__ __forceinline__ void mma_tf32(float* c, uint32_t a0, uint32_t a1,
                                         uint32_t a2, uint32_t a3,
                                         uint32_t b0, uint32_t b1) {
    asm volatile("mma.sync.aligned.m16n8k8.row.col.f32.tf32.tf32.f32 "
                 "{%0,%1,%2,%3}, {%4,%5,%6,%7}, {%8,%9}, {%0,%1,%2,%3};"
                 : "+f"(c[0]), "+f"(c[1]), "+f"(c[2]), "+f"(c[3])
                 : "r"(a0), "r"(a1), "r"(a2), "r"(a3), "r"(b0), "r"(b1));
}

// ---------------- LayerNorm: one CTA (256 thr) per row of 768 --------------
__global__ void ln_kernel(const float* __restrict__ xin, const float* __restrict__ g,
                          const float* __restrict__ b, float* __restrict__ y)
{
    int row = blockIdx.x, t = threadIdx.x;
    const float* xr = xin + (size_t)row * DD;
    float*       yr = y   + (size_t)row * DD;
    float v0 = xr[t], v1 = xr[t + 256], v2 = xr[t + 512];
    float s  = v0 + v1 + v2;
    float s2 = v0*v0 + v1*v1 + v2*v2;
    __shared__ float rs[8], rs2[8];
    #pragma unroll
    for (int o = 16; o > 0; o >>= 1) {
        s  += __shfl_xor_sync(0xffffffffu, s,  o);
        s2 += __shfl_xor_sync(0xffffffffu, s2, o);
    }
    if ((t & 31) == 0) { rs[t >> 5] = s; rs2[t >> 5] = s2; }
    __syncthreads();
    float ts = 0.f, ts2 = 0.f;
    #pragma unroll
    for (int w = 0; w < 8; w++) { ts += rs[w]; ts2 += rs2[w]; }
    float mu  = ts  * (1.0f / DD);
    float var = ts2 * (1.0f / DD) - mu * mu;
    float inv = rsqrtf(var + 1e-5f);
    yr[t]       = (v0 - mu) * inv * g[t]       + b[t];
    yr[t + 256] = (v1 - mu) * inv * g[t + 256] + b[t + 256];
    yr[t + 512] = (v2 - mu) * inv * g[t + 512] + b[t + 512];
}

// ============ 3xTF32 QKV GEMM: C[R,2304] = A[R,768] W[2304,768]^T + bias ===
// CTA tile 128x128, k-chunk 32, 8 warps (2m x 4n), warp tile 64x32.
// Smem: A/W tiles [128][36] fp32, double-buffered.  72 KB dynamic.
#define QK_TILEF   (128 * 36)                  // floats per tile
#define QK_SMEMB   (4 * QK_TILEF * 4)          // bytes (A0,A1,W0,W1)
#define QK_CHUNKS  (DD / 32)                   // 24

__global__ __launch_bounds__(256) void qkv_tf32(const float* __restrict__ A,
                                                const float* __restrict__ W,
                                                const float* __restrict__ bias,
                                                float* __restrict__ C)
{
    extern __shared__ float sm[];
    float* Asm = sm;                     // 2 stages
    float* Wsm = sm + 2 * QK_TILEF;      // 2 stages
    uint32_t sb = smem_u32(sm);

    int tid = threadIdx.x;
    int wid = tid >> 5, lane = tid & 31;
    int gp = lane >> 2, tg = lane & 3;
    int wm = (wid & 1) * 64;
    int wn = (wid >> 1) * 32;
    int m0 = blockIdx.y * 128;
    int n0 = blockIdx.x * 128;

    float acc[4][4][4];
    #pragma unroll
    for (int i = 0; i < 4; i++)
        #pragma unroll
        for (int j = 0; j < 4; j++)
            #pragma unroll
            for (int r = 0; r < 4; r++) acc[i][j][r] = 0.f;

    // ---- async load of one 32-wide k-chunk into stage ----
    auto load_chunk = [&](int c, int stage) {
        int k0 = c * 32;
        uint32_t abase = sb + (uint32_t)(stage * QK_TILEF * 4);
        uint32_t wbase = sb + (uint32_t)((2 + stage) * QK_TILEF * 4);
        #pragma unroll
        for (int i = 0; i < 4; i++) {
            int idx = tid + i * 256;        // 0..1023
            int row = idx >> 3, seg = idx & 7;
            uint32_t doff = (uint32_t)(row * 144 + seg * 16);
            cp_async16(abase + doff, A + (size_t)(m0 + row) * DD + k0 + seg * 4);
            cp_async16(wbase + doff, W + (size_t)(n0 + row) * DD + k0 + seg * 4);
        }
        CP_COMMIT();
    };

    load_chunk(0, 0);
    load_chunk(1, 1);

    for (int c = 0; c < QK_CHUNKS; c++) {
        int s = c & 1;
        CP_WAIT1();
        __syncthreads();
        const float* as = Asm + s * QK_TILEF;
        const float* ws = Wsm + s * QK_TILEF;

        #pragma unroll
        for (int ks = 0; ks < 4; ks++) {
            int k = ks * 8 + tg;
            uint32_t ah[4][4], al[4][4];
            #pragma unroll
            for (int mf = 0; mf < 4; mf++) {
                int r = wm + mf * 16 + gp;
                f32_split(as[r * 36 + k],           ah[mf][0], al[mf][0]);
                f32_split(as[(r + 8) * 36 + k],     ah[mf][1], al[mf][1]);
                f32_split(as[r * 36 + k + 4],       ah[mf][2], al[mf][2]);
                f32_split(as[(r + 8) * 36 + k + 4], ah[mf][3], al[mf][3]);
            }
            uint32_t bh[4][2], bl[4][2];
            #pragma unroll
            for (int nf = 0; nf < 4; nf++) {
                int n = wn + nf * 8 + gp;
                f32_split(ws[n * 36 + k],     bh[nf][0], bl[nf][0]);
                f32_split(ws[n * 36 + k + 4], bh[nf][1], bl[nf][1]);
            }
            #pragma unroll
            for (int mf = 0; mf < 4; mf++)
                #pragma unroll
                for (int nf = 0; nf < 4; nf++) {
                    float* cc = acc[mf][nf];
                    mma_tf32(cc, ah[mf][0], ah[mf][1], ah[mf][2], ah[mf][3],
                             bh[nf][0], bh[nf][1]);
                    mma_tf32(cc, ah[mf][0], ah[mf][1], ah[mf][2], ah[mf][3],
                             bl[nf][0], bl[nf][1]);
                    mma_tf32(cc, al[mf][0], al[mf][1], al[mf][2], al[mf][3],
                             bh[nf][0], bh[nf][1]);
                }
        }
        __syncthreads();
        if (c + 2 < QK_CHUNKS) load_chunk(c + 2, s);
    }

    // ---- epilogue: C = acc + bias ----
    #pragma unroll
    for (int mf = 0; mf < 4; mf++) {
        int r0 = m0 + wm + mf * 16 + gp;
        #pragma unroll
        for (int nf = 0; nf < 4; nf++) {
            int col = n0 + wn + nf * 8 + 2 * tg;
            float b0 = bias[col], b1 = bias[col + 1];
            float2 v0 = make_float2(acc[mf][nf][0] + b0, acc[mf][nf][1] + b1);
            float2 v1 = make_float2(acc[mf][nf][2] + b0, acc[mf][nf][3] + b1);
            *(float2*)(C + (size_t)r0 * TD + col)       = v0;
            *(float2*)(C + (size_t)(r0 + 8) * TD + col) = v1;
        }
    }
}

// ---------------- row mask: rm[h][l] = sum_e mask[h,e,l] -------------------
__global__ void rowmask_kernel(const float* __restrict__ mask, float* __restrict__ rm)
{
    int h = blockIdx.x, l = threadIdx.x;
    float s = 0.f;
    for (int e = 0; e < EE; e++) s += mask[((size_t)h * EE + e) * LL + l];
    rm[h * LL + l] = s;
}

// ---------------- row scores: S_h[i,j] = sum_{s,c} Q[s,i,h,c] K[s,j,h,c] ---
__global__ __launch_bounds__(64) void rowscore_kernel(const float* __restrict__ qkv,
                                                      float* __restrict__ spart)
{
    __shared__ float As[16][64];
    __shared__ float Bs[16][64];
    int h = blockIdx.z >> 3, ks = blockIdx.z & 7;
    int i0 = blockIdx.y * 64, j0 = blockIdx.x * 64;
    int t = threadIdx.x, ty = t >> 3, tx = t & 7;
    float acc[8][8] = {};

    for (int s = ks * 16; s < ks * 16 + 16; s++) {
        const float* qb = qkv + (size_t)(s * LL + i0 + t) * TD + h * DHH;
        const float* kb = qkv + (size_t)(s * LL + j0 + t) * TD + DD + h * DHH;
        for (int c0 = 0; c0 < DHH; c0 += 16) {
            #pragma unroll
            for (int q = 0; q < 4; q++) {
                float4 a = *(const float4*)(qb + c0 + q * 4);
                float4 b = *(const float4*)(kb + c0 + q * 4);
                As[q*4+0][t]=a.x; As[q*4+1][t]=a.y; As[q*4+2][t]=a.z; As[q*4+3][t]=a.w;
                Bs[q*4+0][t]=b.x; Bs[q*4+1][t]=b.y; Bs[q*4+2][t]=b.z; Bs[q*4+3][t]=b.w;
            }
            __syncthreads();
            #pragma unroll
            for (int k = 0; k < 16; k++) {
                float a[8], b[8];
                *(float4*)(a)   = *(const float4*)&As[k][ty*8];
                *(float4*)(a+4) = *(const float4*)&As[k][ty*8+4];
                *(float4*)(b)   = *(const float4*)&Bs[k][tx*8];
                *(float4*)(b+4) = *(const float4*)&Bs[k][tx*8+4];
                #pragma unroll
                for (int u = 0; u < 8; u++)
                    #pragma unroll
                    for (int v = 0; v < 8; v++) acc[u][v] += a[u] * b[v];
            }
            __syncthreads();
        }
    }
    float* outp = spart + (size_t)(ks * HH + h) * (LL * LL);
    #pragma unroll
    for (int u = 0; u < 8; u++) {
        float* orow = outp + (size_t)(i0 + ty*8 + u) * LL + j0 + tx*8;
        #pragma unroll
        for (int v = 0; v < 8; v++) orow[v] = acc[u][v];
    }
}

// ---------------- row softmax ----------------------------------------------
__global__ void rowsoftmax_kernel(const float* __restrict__ spart,
                                  const float* __restrict__ rm,
                                  float* __restrict__ maps)
{
    int i = blockIdx.x, h = blockIdx.y, j = threadIdx.x;
    size_t idx = ((size_t)h * LL + i) * LL + j;
    float v = rm[h * LL + j];
    #pragma unroll
    for (int p = 0; p < 8; p++) v += spart[(size_t)p * (HH * (size_t)LL * LL) + idx];
    __shared__ float r1[8], r2[8];
    float m = v;
    #pragma unroll
    for (int o = 16; o > 0; o >>= 1) m = fmaxf(m, __shfl_xor_sync(0xffffffffu, m, o));
    if ((j & 31) == 0) r1[j >> 5] = m;
    __syncthreads();
    m = r1[0];
    #pragma unroll
    for (int w = 1; w < 8; w++) m = fmaxf(m, r1[w]);
    float e = __expf(v - m);
    float s = e;
    #pragma unroll
    for (int o = 16; o > 0; o >>= 1) s += __shfl_xor_sync(0xffffffffu, s, o);
    if ((j & 31) == 0) r2[j >> 5] = s;
    __syncthreads();
    s = 0.f;
    #pragma unroll
    for (int w = 0; w < 8; w++) s += r2[w];
    maps[idx] = e / s;
}

// ---------------- row out: x1 = x + maps_h @ V_h ---------------------------
__global__ __launch_bounds__(64) void rowout_kernel(const float* __restrict__ maps,
                                                    const float* __restrict__ qkv,
                                                    const float* __restrict__ xin,
                                                    float* __restrict__ xout)
{
    __shared__ float As[16][64];
    __shared__ float Bs[16][64];
    int h = blockIdx.z, s = blockIdx.y, i0 = blockIdx.x * 64;
    int t = threadIdx.x, ty = t >> 3, tx = t & 7;
    float acc[8][8] = {};
    const float* arow = maps + (size_t)(h * LL + i0 + t) * LL;

    for (int k0 = 0; k0 < LL; k0 += 16) {
        #pragma unroll
        for (int q = 0; q < 4; q++) {
            float4 a = *(const float4*)(arow + k0 + q * 4);
            As[q*4+0][t]=a.x; As[q*4+1][t]=a.y; As[q*4+2][t]=a.z; As[q*4+3][t]=a.w;
        }
        #pragma unroll
        for (int q = 0; q < 4; q++) {
            int f4 = t * 4 + q;
            int j  = f4 >> 4, c4 = f4 & 15;
            float4 b = *(const float4*)(qkv + (size_t)(s * LL + k0 + j) * TD
                                        + 2 * DD + h * DHH + c4 * 4);
            *(float4*)&Bs[j][c4 * 4] = b;
        }
        __syncthreads();
        #pragma unroll
        for (int k = 0; k < 16; k++) {
            float a[8], b[8];
            *(float4*)(a)   = *(const float4*)&As[k][ty*8];
            *(float4*)(a+4) = *(const float4*)&As[k][ty*8+4];
            *(float4*)(b)   = *(const float4*)&Bs[k][tx*8];
            *(float4*)(b+4) = *(const float4*)&Bs[k][tx*8+4];
            #pragma unroll
            for (int u = 0; u < 8; u++)
                #pragma unroll
                for (int v = 0; v < 8; v++) acc[u][v] += a[u] * b[v];
        }
        __syncthreads();
    }
    #pragma unroll
    for (int u = 0; u < 8; u++) {
        int i = i0 + ty * 8 + u;
        size_t base = (size_t)(s * LL + i) * DD + h * DHH + tx * 8;
        #pragma unroll
        for (int v2 = 0; v2 < 8; v2 += 4) {
            float4 xi = *(const float4*)(xin + base + v2);
            float4 o;
            o.x = xi.x + acc[u][v2+0]; o.y = xi.y + acc[u][v2+1];
            o.z = xi.z + acc[u][v2+2]; o.w = xi.w + acc[u][v2+3];
            *(float4*)(xout + base + v2) = o;
        }
    }
}

// ---------------- fused column attention -----------------------------------
#define STQ 132
#define STV 68
#define COL_SMEM_BYTES ((128*STQ + 128*STV + 128) * 4)

__global__ __launch_bounds__(256) void colfused_kernel(const float* __restrict__ qkv,
                                                       const float* __restrict__ mask,
                                                       const float* __restrict__ xin,
                                                       float* __restrict__ out)
{
    extern __shared__ float cs[];
    float* QT = cs;
    float* KT = cs + 64 * STQ;
    float* ST = cs;
    float* Vs = cs + 128 * STQ;
    float* mk = Vs + 128 * STV;
    int l = blockIdx.x, h = blockIdx.y;
    int t = threadIdx.x;

    {
        int j = t >> 1, half = t & 1;
        const float* base = qkv + (size_t)(j * LL + l) * TD + h * DHH + half * 32;
        #pragma unroll
        for (int q = 0; q < 8; q++) {
            int c = half * 32 + q * 4;
            float4 qv = *(const float4*)(base + q * 4);
            float4 kv = *(const float4*)(base + DD + q * 4);
            float4 vv = *(const float4*)(base + 2 * DD + q * 4);
            QT[(c+0)*STQ + j] = qv.x; QT[(c+1)*STQ + j] = qv.y;
            QT[(c+2)*STQ + j] = qv.z; QT[(c+3)*STQ + j] = qv.w;
            KT[(c+0)*STQ + j] = kv.x; KT[(c+1)*STQ + j] = kv.y;
            KT[(c+2)*STQ + j] = kv.z; KT[(c+3)*STQ + j] = kv.w;
            *(float4*)&Vs[j * STV + c] = vv;
        }
        if (t < EE) mk[t] = mask[((size_t)h * EE + t) * LL + l];
    }
    __syncthreads();

    int ty = t >> 4, tx = t & 15;
    float accS[8][8] = {};
    #pragma unroll 4
    for (int c = 0; c < DHH; c++) {
        float a[8], b[8];
        *(float4*)(a)   = *(const float4*)&QT[c*STQ + ty*8];
        *(float4*)(a+4) = *(const float4*)&QT[c*STQ + ty*8+4];
        *(float4*)(b)   = *(const float4*)&KT[c*STQ + tx*8];
        *(float4*)(b+4) = *(const float4*)&KT[c*STQ + tx*8+4];
        #pragma unroll
        for (int u = 0; u < 8; u++)
            #pragma unroll
            for (int v = 0; v < 8; v++) accS[u][v] += a[u] * b[v];
    }
    __syncthreads();
    #pragma unroll
    for (int u = 0; u < 8; u++)
        #pragma unroll
        for (int v = 0; v < 8; v++)
            ST[(tx*8 + v) * STQ + (ty*8 + u)] = accS[u][v];
    __syncthreads();

    {
        int i = t >> 1, half = t & 1;
        float m = -1e30f;
        for (int tt = 0; tt < 64; tt++) {
            int j = half * 64 + tt;
            m = fmaxf(m, ST[j*STQ + i] + mk[j]);
        }
        m = fmaxf(m, __shfl_xor_sync(0xffffffffu, m, 1));
        float ssum = 0.f;
        for (int tt = 0; tt < 64; tt++) {
            int j = half * 64 + tt;
            float e = __expf(ST[j*STQ + i] + mk[j] - m);
            ST[j*STQ + i] = e;
            ssum += e;
        }
        ssum += __shfl_xor_sync(0xffffffffu, ssum, 1);
        float inv = 1.f / ssum;
        for (int tt = 0; tt < 64; tt++) {
            int j = half * 64 + tt;
            ST[j*STQ + i] *= inv;
        }
    }
    __syncthreads();

    {
        int ti = t >> 4, tc = t & 15;
        float accO[8][4] = {};
        for (int j = 0; j < EE; j++) {
            float p[8];
            *(float4*)(p)   = *(const float4*)&ST[j*STQ + ti*8];
            *(float4*)(p+4) = *(const float4*)&ST[j*STQ + ti*8+4];
            float4 vv = *(const float4*)&Vs[j*STV + tc*4];
            #pragma unroll
            for (int u = 0; u < 8; u++) {
                accO[u][0] += p[u] * vv.x; accO[u][1] += p[u] * vv.y;
                accO[u][2] += p[u] * vv.z; accO[u][3] += p[u] * vv.w;
            }
        }
        #pragma unroll
        for (int u = 0; u < 8; u++) {
            int i = ti * 8 + u;
            size_t base = (size_t)(i * LL + l) * DD + h * DHH + tc * 4;
            float4 xi = *(const float4*)(xin + base);
            float4 o;
            o.x = xi.x + accO[u][0]; o.y = xi.y + accO[u][1];
            o.z = xi.z + accO[u][2]; o.w = xi.w + accO[u][3];
            *(float4*)(out + base) = o;
        }
    }
}

// ---------------- launch ---------------------------------------------------
extern "C" void kernel_launch(void* const* d_in, const int* in_sizes, int n_in,
                              void* d_out, int out_size)
{
    const float* x     = (const float*)d_in[0];
    const float* mask  = (const float*)d_in[1];
    const float* w_row = (const float*)d_in[2];
    const float* b_row = (const float*)d_in[3];
    const float* w_col = (const float*)d_in[4];
    const float* b_col = (const float*)d_in[5];
    const float* g1    = (const float*)d_in[6];
    const float* be1   = (const float*)d_in[7];
    const float* g2    = (const float*)d_in[8];
    const float* be2   = (const float*)d_in[9];
    float* out = (float*)d_out;

    float *p_xn, *p_qkv, *p_x1, *p_spart, *p_maps, *p_rm;
    cudaGetSymbolAddress((void**)&p_xn,    g_xn);
    cudaGetSymbolAddress((void**)&p_qkv,   g_qkv);
    cudaGetSymbolAddress((void**)&p_x1,    g_x1);
    cudaGetSymbolAddress((void**)&p_spart, g_spart);
    cudaGetSymbolAddress((void**)&p_maps,  g_maps);
    cudaGetSymbolAddress((void**)&p_rm,    g_rm);

    cudaFuncSetAttribute(qkv_tf32,
                         cudaFuncAttributeMaxDynamicSharedMemorySize, QK_SMEMB);
    cudaFuncSetAttribute(colfused_kernel,
                         cudaFuncAttributeMaxDynamicSharedMemorySize, COL_SMEM_BYTES);

    // ---- row attention ----
    ln_kernel<<<RR, 256>>>(x, g1, be1, p_xn);
    qkv_tf32<<<dim3(TD / 128, RR / 128), 256, QK_SMEMB>>>(p_xn, w_row, b_row, p_qkv);
    rowmask_kernel<<<HH, LL>>>(mask, p_rm);
    rowscore_kernel<<<dim3(4, 4, HH * 8), 64>>>(p_qkv, p_spart);
    rowsoftmax_kernel<<<dim3(LL, HH), LL>>>(p_spart, p_rm, p_maps);
    rowout_kernel<<<dim3(4, EE, HH), 64>>>(p_maps, p_qkv, x, p_x1);

    // ---- column attention ----
    ln_kernel<<<RR, 256>>>(p_x1, g2, be2, p_xn);
    qkv_tf32<<<dim3(TD / 128, RR / 128), 256, QK_SMEMB>>>(p_xn, w_col, b_col, p_qkv);
    colfused_kernel<<<dim3(LL, HH), 256, COL_SMEM_BYTES>>>(p_qkv, mask, p_x1, out);
}

// round 9
// speedup vs baseline: 2.0175x; 1.4200x over previous
#include <cuda_runtime.h>
#include <cuda_fp16.h>
#include <cstdint>

// Problem constants
#define EE 128          // E (rows / MSA depth)
#define LL 256          // L (sequence length)
#define HH 12           // heads
#define DHH 64          // head dim
#define DD 768          // D = H*DH
#define TD 2304         // 3*D
#define RR (EE*LL)      // 32768 rows

// ---------------- scratch (device globals; no allocation allowed) ----------
__device__ __align__(256) __half g_ah [(size_t)RR * DD];           // LN out hi (fp16)
__device__ __align__(256) __half g_al [(size_t)RR * DD];           // LN out lo (fp16)
__device__ __align__(256) __half g_wh [(size_t)TD * DD];           // W hi
__device__ __align__(256) __half g_wl [(size_t)TD * DD];           // W lo
__device__ __align__(256) float g_qkv [(size_t)RR * TD];           // qkv projection
__device__ __align__(256) float g_x1  [(size_t)RR * DD];           // x + row_out
__device__ __align__(256) float g_spart[(size_t)8 * HH * LL * LL]; // split-K partials
__device__ __align__(256) float g_maps[(size_t)HH * LL * LL];      // row attention maps
__device__ __align__(256) float g_rm  [HH * LL];                   // row mask

// ============================ helpers ======================================
__device__ __forceinline__ uint32_t smem_u32(const void* p) {
    uint32_t a;
    asm("{ .reg .u64 t; cvta.to.shared.u64 t, %1; cvt.u32.u64 %0, t; }"
        : "=r"(a) : "l"(p));
    return a;
}
__device__ __forceinline__ void cp_async16(uint32_t dst, const void* src) {
    asm volatile("cp.async.cg.shared.global [%0], [%1], 16;\n"
                 :: "r"(dst), "l"(src) : "memory");
}
#define CP_COMMIT() asm volatile("cp.async.commit_group;" ::: "memory")
#define CP_WAIT1()  asm volatile("cp.async.wait_group 1;" ::: "memory")

__device__ __forceinline__ void mma_f16(float* c, uint32_t a0, uint32_t a1,
                                        uint32_t a2, uint32_t a3,
                                        uint32_t b0, uint32_t b1) {
    asm volatile("mma.sync.aligned.m16n8k16.row.col.f32.f16.f16.f32 "
                 "{%0,%1,%2,%3}, {%4,%5,%6,%7}, {%8,%9}, {%0,%1,%2,%3};"
                 : "+f"(c[0]), "+f"(c[1]), "+f"(c[2]), "+f"(c[3])
                 : "r"(a0), "r"(a1), "r"(a2), "r"(a3), "r"(b0), "r"(b1));
}

// split fp32 -> fp16 hi + fp16 lo
__device__ __forceinline__ void f16_split(float x, __half& h, __half& l) {
    h = __float2half_rn(x);
    l = __float2half_rn(x - __half2float(h));
}

// ---------- LayerNorm + fp16 2-way split: one CTA (256 thr) per row --------
__global__ void ln_split_kernel(const float* __restrict__ xin, const float* __restrict__ g,
                                const float* __restrict__ b,
                                __half* __restrict__ yh, __half* __restrict__ yl)
{
    int row = blockIdx.x, t = threadIdx.x;
    const float* xr = xin + (size_t)row * DD;
    float v0 = xr[t], v1 = xr[t + 256], v2 = xr[t + 512];
    float s  = v0 + v1 + v2;
    float s2 = v0*v0 + v1*v1 + v2*v2;
    __shared__ float rs[8], rs2[8];
    #pragma unroll
    for (int o = 16; o > 0; o >>= 1) {
        s  += __shfl_xor_sync(0xffffffffu, s,  o);
        s2 += __shfl_xor_sync(0xffffffffu, s2, o);
    }
    if ((t & 31) == 0) { rs[t >> 5] = s; rs2[t >> 5] = s2; }
    __syncthreads();
    float ts = 0.f, ts2 = 0.f;
    #pragma unroll
    for (int w = 0; w < 8; w++) { ts += rs[w]; ts2 += rs2[w]; }
    float mu  = ts  * (1.0f / DD);
    float var = ts2 * (1.0f / DD) - mu * mu;
    float inv = rsqrtf(var + 1e-5f);
    __half* yhr = yh + (size_t)row * DD;
    __half* ylr = yl + (size_t)row * DD;
    #pragma unroll
    for (int q = 0; q < 3; q++) {
        int k = t + q * 256;
        float v = (q == 0) ? v0 : (q == 1) ? v1 : v2;
        float yv = (v - mu) * inv * g[k] + b[k];
        __half h, l;
        f16_split(yv, h, l);
        yhr[k] = h; ylr[k] = l;
    }
}

// ---------- weight fp16 split: W[2304,768] -> wh, wl -----------------------
__global__ void wsplit_kernel(const float* __restrict__ w,
                              __half* __restrict__ wh, __half* __restrict__ wl)
{
    int row = blockIdx.x, t = threadIdx.x;
    const float* wr = w + (size_t)row * DD;
    __half* hr = wh + (size_t)row * DD;
    __half* lr = wl + (size_t)row * DD;
    #pragma unroll
    for (int q = 0; q < 3; q++) {
        int k = t + q * 256;
        __half h, l;
        f16_split(wr[k], h, l);
        hr[k] = h; lr[k] = l;
    }
}

// ============ 3xFP16 QKV GEMM: C[R,2304] = A[R,768] W[2304,768]^T + bias ===
// CTA tile 128x128, k-chunk 32 (two k16 steps), 8 warps (2m x 4n), warp 64x32.
// Smem per stage: 4 fp16 tiles [128 rows x 32 k] stride 80B = 40 KB; x2 = 80 KB.
#define QF_ROWB    80                          // bytes per smem row
#define QF_TILEB   (128 * QF_ROWB)             // 10240 B per tile
#define QF_STAGEB  (4 * QF_TILEB)              // 40960 B
#define QF_SMEMB   (2 * QF_STAGEB)             // 81920 B
#define QF_CHUNKS  (DD / 32)                   // 24

__global__ __launch_bounds__(256) void qkv_fp16(const __half* __restrict__ Ah,
                                                const __half* __restrict__ Al,
                                                const __half* __restrict__ Wh,
                                                const __half* __restrict__ Wl,
                                                const float* __restrict__ bias,
                                                float* __restrict__ C)
{
    extern __shared__ __align__(16) char smc[];
    uint32_t sb = smem_u32(smc);

    int tid = threadIdx.x;
    int wid = tid >> 5, lane = tid & 31;
    int gp = lane >> 2, tg = lane & 3;
    int wm = (wid & 1) * 64;
    int wn = (wid >> 1) * 32;
    int m0 = blockIdx.y * 128;
    int n0 = blockIdx.x * 128;

    float acc[4][4][4];
    #pragma unroll
    for (int i = 0; i < 4; i++)
        #pragma unroll
        for (int j = 0; j < 4; j++)
            #pragma unroll
            for (int r = 0; r < 4; r++) acc[i][j][r] = 0.f;

    // tiles in stage: 0=Ah 1=Al 2=Wh 3=Wl
    const __half* gsrc[4] = {Ah, Al, Wh, Wl};

    auto load_chunk = [&](int c, int stage) {
        int k0 = c * 32;
        uint32_t base = sb + (uint32_t)(stage * QF_STAGEB);
        #pragma unroll
        for (int i = 0; i < 8; i++) {
            int idx = tid + i * 256;           // 0..2047
            int t4   = idx >> 9;               // tile 0..3
            int r    = (idx >> 2) & 127;       // row 0..127
            int seg  = idx & 3;                // 16B segment
            int grow = (t4 < 2 ? m0 : n0) + r;
            uint32_t dst = base + (uint32_t)(t4 * QF_TILEB + r * QF_ROWB + seg * 16);
            cp_async16(dst, gsrc[t4] + (size_t)grow * DD + k0 + seg * 8);
        }
        CP_COMMIT();
    };

    load_chunk(0, 0);
    load_chunk(1, 1);

    for (int c = 0; c < QF_CHUNKS; c++) {
        int s = c & 1;
        CP_WAIT1();
        __syncthreads();
        const char* stg = smc + s * QF_STAGEB;
        const char* sAh = stg;
        const char* sAl = stg + QF_TILEB;
        const char* sWh = stg + 2 * QF_TILEB;
        const char* sWl = stg + 3 * QF_TILEB;

        #pragma unroll
        for (int ks = 0; ks < 2; ks++) {
            int kb = (ks * 16 + 2 * tg) * 2;   // byte offset of k pair
            // --- load Ah, Wh fragments; hh pass ---
            uint32_t fAh[4][4];
            #pragma unroll
            for (int mf = 0; mf < 4; mf++) {
                int r = wm + mf * 16 + gp;
                fAh[mf][0] = *(const uint32_t*)(sAh + r * QF_ROWB + kb);
                fAh[mf][1] = *(const uint32_t*)(sAh + (r + 8) * QF_ROWB + kb);
                fAh[mf][2] = *(const uint32_t*)(sAh + r * QF_ROWB + kb + 16);
                fAh[mf][3] = *(const uint32_t*)(sAh + (r + 8) * QF_ROWB + kb + 16);
            }
            uint32_t fWh[4][2];
            #pragma unroll
            for (int nf = 0; nf < 4; nf++) {
                int n = wn + nf * 8 + gp;
                fWh[nf][0] = *(const uint32_t*)(sWh + n * QF_ROWB + kb);
                fWh[nf][1] = *(const uint32_t*)(sWh + n * QF_ROWB + kb + 16);
            }
            #pragma unroll
            for (int mf = 0; mf < 4; mf++)
                #pragma unroll
                for (int nf = 0; nf < 4; nf++)
                    mma_f16(acc[mf][nf], fAh[mf][0], fAh[mf][1], fAh[mf][2],
                            fAh[mf][3], fWh[nf][0], fWh[nf][1]);
            // --- load Al fragments; lh pass (Al x Wh) ---
            {
                uint32_t fAl[4][4];
                #pragma unroll
                for (int mf = 0; mf < 4; mf++) {
                    int r = wm + mf * 16 + gp;
                    fAl[mf][0] = *(const uint32_t*)(sAl + r * QF_ROWB + kb);
                    fAl[mf][1] = *(const uint32_t*)(sAl + (r + 8) * QF_ROWB + kb);
                    fAl[mf][2] = *(const uint32_t*)(sAl + r * QF_ROWB + kb + 16);
                    fAl[mf][3] = *(const uint32_t*)(sAl + (r + 8) * QF_ROWB + kb + 16);
                }
                #pragma unroll
                for (int mf = 0; mf < 4; mf++)
                    #pragma unroll
                    for (int nf = 0; nf < 4; nf++)
                        mma_f16(acc[mf][nf], fAl[mf][0], fAl[mf][1], fAl[mf][2],
                                fAl[mf][3], fWh[nf][0], fWh[nf][1]);
            }
            // --- load Wl fragments; hl pass (Ah x Wl) ---
            {
                uint32_t fWl[4][2];
                #pragma unroll
                for (int nf = 0; nf < 4; nf++) {
                    int n = wn + nf * 8 + gp;
                    fWl[nf][0] = *(const uint32_t*)(sWl + n * QF_ROWB + kb);
                    fWl[nf][1] = *(const uint32_t*)(sWl + n * QF_ROWB + kb + 16);
                }
                #pragma unroll
                for (int mf = 0; mf < 4; mf++)
                    #pragma unroll
                    for (int nf = 0; nf < 4; nf++)
                        mma_f16(acc[mf][nf], fAh[mf][0], fAh[mf][1], fAh[mf][2],
                                fAh[mf][3], fWl[nf][0], fWl[nf][1]);
            }
        }
        __syncthreads();
        if (c + 2 < QF_CHUNKS) load_chunk(c + 2, s);
    }

    // ---- epilogue: C = acc + bias ----
    #pragma unroll
    for (int mf = 0; mf < 4; mf++) {
        int r0 = m0 + wm + mf * 16 + gp;
        #pragma unroll
        for (int nf = 0; nf < 4; nf++) {
            int col = n0 + wn + nf * 8 + 2 * tg;
            float b0 = bias[col], b1 = bias[col + 1];
            float2 v0 = make_float2(acc[mf][nf][0] + b0, acc[mf][nf][1] + b1);
            float2 v1 = make_float2(acc[mf][nf][2] + b0, acc[mf][nf][3] + b1);
            *(float2*)(C + (size_t)r0 * TD + col)       = v0;
            *(float2*)(C + (size_t)(r0 + 8) * TD + col) = v1;
        }
    }
}

// ---------------- row mask: rm[h][l] = sum_e mask[h,e,l] -------------------
__global__ void rowmask_kernel(const float* __restrict__ mask, float* __restrict__ rm)
{
    int h = blockIdx.x, l = threadIdx.x;
    float s = 0.f;
    for (int e = 0; e < EE; e++) s += mask[((size_t)h * EE + e) * LL + l];
    rm[h * LL + l] = s;
}

// ---------------- row scores: S_h[i,j] = sum_{s,c} Q[s,i,h,c] K[s,j,h,c] ---
__global__ __launch_bounds__(64) void rowscore_kernel(const float* __restrict__ qkv,
                                                      float* __restrict__ spart)
{
    __shared__ float As[16][64];
    __shared__ float Bs[16][64];
    int h = blockIdx.z >> 3, ks = blockIdx.z & 7;
    int i0 = blockIdx.y * 64, j0 = blockIdx.x * 64;
    int t = threadIdx.x, ty = t >> 3, tx = t & 7;
    float acc[8][8] = {};

    for (int s = ks * 16; s < ks * 16 + 16; s++) {
        const float* qb = qkv + (size_t)(s * LL + i0 + t) * TD + h * DHH;
        const float* kb = qkv + (size_t)(s * LL + j0 + t) * TD + DD + h * DHH;
        for (int c0 = 0; c0 < DHH; c0 += 16) {
            #pragma unroll
            for (int q = 0; q < 4; q++) {
                float4 a = *(const float4*)(qb + c0 + q * 4);
                float4 b = *(const float4*)(kb + c0 + q * 4);
                As[q*4+0][t]=a.x; As[q*4+1][t]=a.y; As[q*4+2][t]=a.z; As[q*4+3][t]=a.w;
                Bs[q*4+0][t]=b.x; Bs[q*4+1][t]=b.y; Bs[q*4+2][t]=b.z; Bs[q*4+3][t]=b.w;
            }
            __syncthreads();
            #pragma unroll
            for (int k = 0; k < 16; k++) {
                float a[8], b[8];
                *(float4*)(a)   = *(const float4*)&As[k][ty*8];
                *(float4*)(a+4) = *(const float4*)&As[k][ty*8+4];
                *(float4*)(b)   = *(const float4*)&Bs[k][tx*8];
                *(float4*)(b+4) = *(const float4*)&Bs[k][tx*8+4];
                #pragma unroll
                for (int u = 0; u < 8; u++)
                    #pragma unroll
                    for (int v = 0; v < 8; v++) acc[u][v] += a[u] * b[v];
            }
            __syncthreads();
        }
    }
    float* outp = spart + (size_t)(ks * HH + h) * (LL * LL);
    #pragma unroll
    for (int u = 0; u < 8; u++) {
        float* orow = outp + (size_t)(i0 + ty*8 + u) * LL + j0 + tx*8;
        #pragma unroll
        for (int v = 0; v < 8; v++) orow[v] = acc[u][v];
    }
}

// ---------------- row softmax ----------------------------------------------
__global__ void rowsoftmax_kernel(const float* __restrict__ spart,
                                  const float* __restrict__ rm,
                                  float* __restrict__ maps)
{
    int i = blockIdx.x, h = blockIdx.y, j = threadIdx.x;
    size_t idx = ((size_t)h * LL + i) * LL + j;
    float v = rm[h * LL + j];
    #pragma unroll
    for (int p = 0; p < 8; p++) v += spart[(size_t)p * (HH * (size_t)LL * LL) + idx];
    __shared__ float r1[8], r2[8];
    float m = v;
    #pragma unroll
    for (int o = 16; o > 0; o >>= 1) m = fmaxf(m, __shfl_xor_sync(0xffffffffu, m, o));
    if ((j & 31) == 0) r1[j >> 5] = m;
    __syncthreads();
    m = r1[0];
    #pragma unroll
    for (int w = 1; w < 8; w++) m = fmaxf(m, r1[w]);
    float e = __expf(v - m);
    float s = e;
    #pragma unroll
    for (int o = 16; o > 0; o >>= 1) s += __shfl_xor_sync(0xffffffffu, s, o);
    if ((j & 31) == 0) r2[j >> 5] = s;
    __syncthreads();
    s = 0.f;
    #pragma unroll
    for (int w = 0; w < 8; w++) s += r2[w];
    maps[idx] = e / s;
}

// ---------------- row out: x1 = x + maps_h @ V_h ---------------------------
__global__ __launch_bounds__(64) void rowout_kernel(const float* __restrict__ maps,
                                                    const float* __restrict__ qkv,
                                                    const float* __restrict__ xin,
                                                    float* __restrict__ xout)
{
    __shared__ float As[16][64];
    __shared__ float Bs[16][64];
    int h = blockIdx.z, s = blockIdx.y, i0 = blockIdx.x * 64;
    int t = threadIdx.x, ty = t >> 3, tx = t & 7;
    float acc[8][8] = {};
    const float* arow = maps + (size_t)(h * LL + i0 + t) * LL;

    for (int k0 = 0; k0 < LL; k0 += 16) {
        #pragma unroll
        for (int q = 0; q < 4; q++) {
            float4 a = *(const float4*)(arow + k0 + q * 4);
            As[q*4+0][t]=a.x; As[q*4+1][t]=a.y; As[q*4+2][t]=a.z; As[q*4+3][t]=a.w;
        }
        #pragma unroll
        for (int q = 0; q < 4; q++) {
            int f4 = t * 4 + q;
            int j  = f4 >> 4, c4 = f4 & 15;
            float4 b = *(const float4*)(qkv + (size_t)(s * LL + k0 + j) * TD
                                        + 2 * DD + h * DHH + c4 * 4);
            *(float4*)&Bs[j][c4 * 4] = b;
        }
        __syncthreads();
        #pragma unroll
        for (int k = 0; k < 16; k++) {
            float a[8], b[8];
            *(float4*)(a)   = *(const float4*)&As[k][ty*8];
            *(float4*)(a+4) = *(const float4*)&As[k][ty*8+4];
            *(float4*)(b)   = *(const float4*)&Bs[k][tx*8];
            *(float4*)(b+4) = *(const float4*)&Bs[k][tx*8+4];
            #pragma unroll
            for (int u = 0; u < 8; u++)
                #pragma unroll
                for (int v = 0; v < 8; v++) acc[u][v] += a[u] * b[v];
        }
        __syncthreads();
    }
    #pragma unroll
    for (int u = 0; u < 8; u++) {
        int i = i0 + ty * 8 + u;
        size_t base = (size_t)(s * LL + i) * DD + h * DHH + tx * 8;
        #pragma unroll
        for (int v2 = 0; v2 < 8; v2 += 4) {
            float4 xi = *(const float4*)(xin + base + v2);
            float4 o;
            o.x = xi.x + acc[u][v2+0]; o.y = xi.y + acc[u][v2+1];
            o.z = xi.z + acc[u][v2+2]; o.w = xi.w + acc[u][v2+3];
            *(float4*)(xout + base + v2) = o;
        }
    }
}

// ---------------- fused column attention -----------------------------------
#define STQ 132
#define STV 68
#define COL_SMEM_BYTES ((128*STQ + 128*STV + 128) * 4)

__global__ __launch_bounds__(256) void colfused_kernel(const float* __restrict__ qkv,
                                                       const float* __restrict__ mask,
                                                       const float* __restrict__ xin,
                                                       float* __restrict__ out)
{
    extern __shared__ float cs[];
    float* QT = cs;
    float* KT = cs + 64 * STQ;
    float* ST = cs;
    float* Vs = cs + 128 * STQ;
    float* mk = Vs + 128 * STV;
    int l = blockIdx.x, h = blockIdx.y;
    int t = threadIdx.x;

    {
        int j = t >> 1, half = t & 1;
        const float* base = qkv + (size_t)(j * LL + l) * TD + h * DHH + half * 32;
        #pragma unroll
        for (int q = 0; q < 8; q++) {
            int c = half * 32 + q * 4;
            float4 qv = *(const float4*)(base + q * 4);
            float4 kv = *(const float4*)(base + DD + q * 4);
            float4 vv = *(const float4*)(base + 2 * DD + q * 4);
            QT[(c+0)*STQ + j] = qv.x; QT[(c+1)*STQ + j] = qv.y;
            QT[(c+2)*STQ + j] = qv.z; QT[(c+3)*STQ + j] = qv.w;
            KT[(c+0)*STQ + j] = kv.x; KT[(c+1)*STQ + j] = kv.y;
            KT[(c+2)*STQ + j] = kv.z; KT[(c+3)*STQ + j] = kv.w;
            *(float4*)&Vs[j * STV + c] = vv;
        }
        if (t < EE) mk[t] = mask[((size_t)h * EE + t) * LL + l];
    }
    __syncthreads();

    int ty = t >> 4, tx = t & 15;
    float accS[8][8] = {};
    #pragma unroll 4
    for (int c = 0; c < DHH; c++) {
        float a[8], b[8];
        *(float4*)(a)   = *(const float4*)&QT[c*STQ + ty*8];
        *(float4*)(a+4) = *(const float4*)&QT[c*STQ + ty*8+4];
        *(float4*)(b)   = *(const float4*)&KT[c*STQ + tx*8];
        *(float4*)(b+4) = *(const float4*)&KT[c*STQ + tx*8+4];
        #pragma unroll
        for (int u = 0; u < 8; u++)
            #pragma unroll
            for (int v = 0; v < 8; v++) accS[u][v] += a[u] * b[v];
    }
    __syncthreads();
    #pragma unroll
    for (int u = 0; u < 8; u++)
        #pragma unroll
        for (int v = 0; v < 8; v++)
            ST[(tx*8 + v) * STQ + (ty*8 + u)] = accS[u][v];
    __syncthreads();

    {
        int i = t >> 1, half = t & 1;
        float m = -1e30f;
        for (int tt = 0; tt < 64; tt++) {
            int j = half * 64 + tt;
            m = fmaxf(m, ST[j*STQ + i] + mk[j]);
        }
        m = fmaxf(m, __shfl_xor_sync(0xffffffffu, m, 1));
        float ssum = 0.f;
        for (int tt = 0; tt < 64; tt++) {
            int j = half * 64 + tt;
            float e = __expf(ST[j*STQ + i] + mk[j] - m);
            ST[j*STQ + i] = e;
            ssum += e;
        }
        ssum += __shfl_xor_sync(0xffffffffu, ssum, 1);
        float inv = 1.f / ssum;
        for (int tt = 0; tt < 64; tt++) {
            int j = half * 64 + tt;
            ST[j*STQ + i] *= inv;
        }
    }
    __syncthreads();

    {
        int ti = t >> 4, tc = t & 15;
        float accO[8][4] = {};
        for (int j = 0; j < EE; j++) {
            float p[8];
            *(float4*)(p)   = *(const float4*)&ST[j*STQ + ti*8];
            *(float4*)(p+4) = *(const float4*)&ST[j*STQ + ti*8+4];
            float4 vv = *(const float4*)&Vs[j*STV + tc*4];
            #pragma unroll
            for (int u = 0; u < 8; u++) {
                accO[u][0] += p[u] * vv.x; accO[u][1] += p[u] * vv.y;
                accO[u][2] += p[u] * vv.z; accO[u][3] += p[u] * vv.w;
            }
        }
        #pragma unroll
        for (int u = 0; u < 8; u++) {
            int i = ti * 8 + u;
            size_t base = (size_t)(i * LL + l) * DD + h * DHH + tc * 4;
            float4 xi = *(const float4*)(xin + base);
            float4 o;
            o.x = xi.x + accO[u][0]; o.y = xi.y + accO[u][1];
            o.z = xi.z + accO[u][2]; o.w = xi.w + accO[u][3];
            *(float4*)(out + base) = o;
        }
    }
}

// ---------------- launch ---------------------------------------------------
extern "C" void kernel_launch(void* const* d_in, const int* in_sizes, int n_in,
                              void* d_out, int out_size)
{
    const float* x     = (const float*)d_in[0];
    const float* mask  = (const float*)d_in[1];
    const float* w_row = (const float*)d_in[2];
    const float* b_row = (const float*)d_in[3];
    const float* w_col = (const float*)d_in[4];
    const float* b_col = (const float*)d_in[5];
    const float* g1    = (const float*)d_in[6];
    const float* be1   = (const float*)d_in[7];
    const float* g2    = (const float*)d_in[8];
    const float* be2   = (const float*)d_in[9];
    float* out = (float*)d_out;

    __half *p_ah, *p_al, *p_wh, *p_wl;
    float *p_qkv, *p_x1, *p_spart, *p_maps, *p_rm;
    cudaGetSymbolAddress((void**)&p_ah,    g_ah);
    cudaGetSymbolAddress((void**)&p_al,    g_al);
    cudaGetSymbolAddress((void**)&p_wh,    g_wh);
    cudaGetSymbolAddress((void**)&p_wl,    g_wl);
    cudaGetSymbolAddress((void**)&p_qkv,   g_qkv);
    cudaGetSymbolAddress((void**)&p_x1,    g_x1);
    cudaGetSymbolAddress((void**)&p_spart, g_spart);
    cudaGetSymbolAddress((void**)&p_maps,  g_maps);
    cudaGetSymbolAddress((void**)&p_rm,    g_rm);

    cudaFuncSetAttribute(qkv_fp16,
                         cudaFuncAttributeMaxDynamicSharedMemorySize, QF_SMEMB);
    cudaFuncSetAttribute(colfused_kernel,
                         cudaFuncAttributeMaxDynamicSharedMemorySize, COL_SMEM_BYTES);

    // ---- row attention ----
    ln_split_kernel<<<RR, 256>>>(x, g1, be1, p_ah, p_al);
    wsplit_kernel<<<TD, 256>>>(w_row, p_wh, p_wl);
    qkv_fp16<<<dim3(TD / 128, RR / 128), 256, QF_SMEMB>>>(
        p_ah, p_al, p_wh, p_wl, b_row, p_qkv);
    rowmask_kernel<<<HH, LL>>>(mask, p_rm);
    rowscore_kernel<<<dim3(4, 4, HH * 8), 64>>>(p_qkv, p_spart);
    rowsoftmax_kernel<<<dim3(LL, HH), LL>>>(p_spart, p_rm, p_maps);
    rowout_kernel<<<dim3(4, EE, HH), 64>>>(p_maps, p_qkv, x, p_x1);

    // ---- column attention ----
    ln_split_kernel<<<RR, 256>>>(p_x1, g2, be2, p_ah, p_al);
    wsplit_kernel<<<TD, 256>>>(w_col, p_wh, p_wl);
    qkv_fp16<<<dim3(TD / 128, RR / 128), 256, QF_SMEMB>>>(
        p_ah, p_al, p_wh, p_wl, b_col, p_qkv);
    colfused_kernel<<<dim3(LL, HH), 256, COL_SMEM_BYTES>>>(p_qkv, mask, p_x1, out);
}

// round 11
// speedup vs baseline: 2.1699x; 1.0756x over previous
#include <cuda_runtime.h>
#include <cuda_fp16.h>
#include <cstdint>

// Problem constants
#define EE 128          // E (rows / MSA depth)
#define LL 256          // L (sequence length)
#define HH 12           // heads
#define DHH 64          // head dim
#define DD 768          // D = H*DH
#define TD 2304         // 3*D
#define RR (EE*LL)      // 32768 rows

// ---------------- scratch (device globals; no allocation allowed) ----------
__device__ __align__(256) __half g_ah [(size_t)RR * DD];           // LN out hi
__device__ __align__(256) __half g_al [(size_t)RR * DD];           // LN out lo
__device__ __align__(256) __half g_wh [(size_t)TD * DD];           // W hi
__device__ __align__(256) __half g_wl [(size_t)TD * DD];           // W lo
__device__ __align__(256) __half g_qh [(size_t)RR * TD];           // qkv hi (row phase)
__device__ __align__(256) __half g_ql [(size_t)RR * TD];           // qkv lo (row phase)
__device__ __align__(256) float g_qkv [(size_t)RR * TD];           // qkv fp32 (col phase)
__device__ __align__(256) float g_x1  [(size_t)RR * DD];           // x + row_out
__device__ __align__(256) float g_spart[(size_t)8 * HH * LL * LL]; // split-K partials
__device__ __align__(256) float g_maps[(size_t)HH * LL * LL];      // row attention maps
__device__ __align__(256) float g_rm  [HH * LL];                   // row mask

// ============================ helpers ======================================
__device__ __forceinline__ uint32_t smem_u32(const void* p) {
    uint32_t a;
    asm("{ .reg .u64 t; cvta.to.shared.u64 t, %1; cvt.u32.u64 %0, t; }"
        : "=r"(a) : "l"(p));
    return a;
}
__device__ __forceinline__ void cp_async16(uint32_t dst, const void* src) {
    asm volatile("cp.async.cg.shared.global [%0], [%1], 16;\n"
                 :: "r"(dst), "l"(src) : "memory");
}
#define CP_COMMIT() asm volatile("cp.async.commit_group;" ::: "memory")
#define CP_WAIT1()  asm volatile("cp.async.wait_group 1;" ::: "memory")

__device__ __forceinline__ void mma_f16(float* c, uint32_t a0, uint32_t a1,
                                        uint32_t a2, uint32_t a3,
                                        uint32_t b0, uint32_t b1) {
    asm volatile("mma.sync.aligned.m16n8k16.row.col.f32.f16.f16.f32 "
                 "{%0,%1,%2,%3}, {%4,%5,%6,%7}, {%8,%9}, {%0,%1,%2,%3};"
                 : "+f"(c[0]), "+f"(c[1]), "+f"(c[2]), "+f"(c[3])
                 : "r"(a0), "r"(a1), "r"(a2), "r"(a3), "r"(b0), "r"(b1));
}

// split fp32 -> fp16 hi + fp16 lo
__device__ __forceinline__ void f16_split(float x, __half& h, __half& l) {
    h = __float2half_rn(x);
    l = __float2half_rn(x - __half2float(h));
}

// ---------- LayerNorm + fp16 2-way split: one CTA (256 thr) per row --------
__global__ void ln_split_kernel(const float* __restrict__ xin, const float* __restrict__ g,
                                const float* __restrict__ b,
                                __half* __restrict__ yh, __half* __restrict__ yl)
{
    int row = blockIdx.x, t = threadIdx.x;
    const float* xr = xin + (size_t)row * DD;
    float v0 = xr[t], v1 = xr[t + 256], v2 = xr[t + 512];
    float s  = v0 + v1 + v2;
    float s2 = v0*v0 + v1*v1 + v2*v2;
    __shared__ float rs[8], rs2[8];
    #pragma unroll
    for (int o = 16; o > 0; o >>= 1) {
        s  += __shfl_xor_sync(0xffffffffu, s,  o);
        s2 += __shfl_xor_sync(0xffffffffu, s2, o);
    }
    if ((t & 31) == 0) { rs[t >> 5] = s; rs2[t >> 5] = s2; }
    __syncthreads();
    float ts = 0.f, ts2 = 0.f;
    #pragma unroll
    for (int w = 0; w < 8; w++) { ts += rs[w]; ts2 += rs2[w]; }
    float mu  = ts  * (1.0f / DD);
    float var = ts2 * (1.0f / DD) - mu * mu;
    float inv = rsqrtf(var + 1e-5f);
    __half* yhr = yh + (size_t)row * DD;
    __half* ylr = yl + (size_t)row * DD;
    #pragma unroll
    for (int q = 0; q < 3; q++) {
        int k = t + q * 256;
        float v = (q == 0) ? v0 : (q == 1) ? v1 : v2;
        float yv = (v - mu) * inv * g[k] + b[k];
        __half h, l;
        f16_split(yv, h, l);
        yhr[k] = h; ylr[k] = l;
    }
}

// ---------- weight fp16 split: W[2304,768] -> wh, wl -----------------------
__global__ void wsplit_kernel(const float* __restrict__ w,
                              __half* __restrict__ wh, __half* __restrict__ wl)
{
    int row = blockIdx.x, t = threadIdx.x;
    const float* wr = w + (size_t)row * DD;
    __half* hr = wh + (size_t)row * DD;
    __half* lr = wl + (size_t)row * DD;
    #pragma unroll
    for (int q = 0; q < 3; q++) {
        int k = t + q * 256;
        __half h, l;
        f16_split(wr[k], h, l);
        hr[k] = h; lr[k] = l;
    }
}

// ============ 3xFP16 QKV GEMM: C[R,2304] = A[R,768] W[2304,768]^T + bias ===
#define QF_ROWB    80
#define QF_TILEB   (128 * QF_ROWB)
#define QF_STAGEB  (4 * QF_TILEB)
#define QF_SMEMB   (2 * QF_STAGEB)             // 81920 B
#define QF_CHUNKS  (DD / 32)                   // 24

__global__ __launch_bounds__(256) void qkv_fp16(const __half* __restrict__ Ah,
                                                const __half* __restrict__ Al,
                                                const __half* __restrict__ Wh,
                                                const __half* __restrict__ Wl,
                                                const float* __restrict__ bias,
                                                float* __restrict__ C,
                                                __half* __restrict__ Ch,
                                                __half* __restrict__ Cl,
                                                int wf32, int wf16)
{
    extern __shared__ __align__(16) char smc[];
    uint32_t sb = smem_u32(smc);

    int tid = threadIdx.x;
    int wid = tid >> 5, lane = tid & 31;
    int gp = lane >> 2, tg = lane & 3;
    int wm = (wid & 1) * 64;
    int wn = (wid >> 1) * 32;
    int m0 = blockIdx.y * 128;
    int n0 = blockIdx.x * 128;

    float acc[4][4][4];
    #pragma unroll
    for (int i = 0; i < 4; i++)
        #pragma unroll
        for (int j = 0; j < 4; j++)
            #pragma unroll
            for (int r = 0; r < 4; r++) acc[i][j][r] = 0.f;

    const __half* gsrc[4] = {Ah, Al, Wh, Wl};

    auto load_chunk = [&](int c, int stage) {
        int k0 = c * 32;
        uint32_t base = sb + (uint32_t)(stage * QF_STAGEB);
        #pragma unroll
        for (int i = 0; i < 8; i++) {
            int idx = tid + i * 256;
            int t4   = idx >> 9;
            int r    = (idx >> 2) & 127;
            int seg  = idx & 3;
            int grow = (t4 < 2 ? m0 : n0) + r;
            uint32_t dst = base + (uint32_t)(t4 * QF_TILEB + r * QF_ROWB + seg * 16);
            cp_async16(dst, gsrc[t4] + (size_t)grow * DD + k0 + seg * 8);
        }
        CP_COMMIT();
    };

    load_chunk(0, 0);
    load_chunk(1, 1);

    for (int c = 0; c < QF_CHUNKS; c++) {
        int s = c & 1;
        CP_WAIT1();
        __syncthreads();
        const char* stg = smc + s * QF_STAGEB;
        const char* sAh = stg;
        const char* sAl = stg + QF_TILEB;
        const char* sWh = stg + 2 * QF_TILEB;
        const char* sWl = stg + 3 * QF_TILEB;

        #pragma unroll
        for (int ks = 0; ks < 2; ks++) {
            int kb = (ks * 16 + 2 * tg) * 2;
            uint32_t fAh[4][4];
            #pragma unroll
            for (int mf = 0; mf < 4; mf++) {
                int r = wm + mf * 16 + gp;
                fAh[mf][0] = *(const uint32_t*)(sAh + r * QF_ROWB + kb);
                fAh[mf][1] = *(const uint32_t*)(sAh + (r + 8) * QF_ROWB + kb);
                fAh[mf][2] = *(const uint32_t*)(sAh + r * QF_ROWB + kb + 16);
                fAh[mf][3] = *(const uint32_t*)(sAh + (r + 8) * QF_ROWB + kb + 16);
            }
            uint32_t fWh[4][2];
            #pragma unroll
            for (int nf = 0; nf < 4; nf++) {
                int n = wn + nf * 8 + gp;
                fWh[nf][0] = *(const uint32_t*)(sWh + n * QF_ROWB + kb);
                fWh[nf][1] = *(const uint32_t*)(sWh + n * QF_ROWB + kb + 16);
            }
            #pragma unroll
            for (int mf = 0; mf < 4; mf++)
                #pragma unroll
                for (int nf = 0; nf < 4; nf++)
                    mma_f16(acc[mf][nf], fAh[mf][0], fAh[mf][1], fAh[mf][2],
                            fAh[mf][3], fWh[nf][0], fWh[nf][1]);
            {
                uint32_t fAl[4][4];
                #pragma unroll
                for (int mf = 0; mf < 4; mf++) {
                    int r = wm + mf * 16 + gp;
                    fAl[mf][0] = *(const uint32_t*)(sAl + r * QF_ROWB + kb);
                    fAl[mf][1] = *(const uint32_t*)(sAl + (r + 8) * QF_ROWB + kb);
                    fAl[mf][2] = *(const uint32_t*)(sAl + r * QF_ROWB + kb + 16);
                    fAl[mf][3] = *(const uint32_t*)(sAl + (r + 8) * QF_ROWB + kb + 16);
                }
                #pragma unroll
                for (int mf = 0; mf < 4; mf++)
                    #pragma unroll
                    for (int nf = 0; nf < 4; nf++)
                        mma_f16(acc[mf][nf], fAl[mf][0], fAl[mf][1], fAl[mf][2],
                                fAl[mf][3], fWh[nf][0], fWh[nf][1]);
            }
            {
                uint32_t fWl[4][2];
                #pragma unroll
                for (int nf = 0; nf < 4; nf++) {
                    int n = wn + nf * 8 + gp;
                    fWl[nf][0] = *(const uint32_t*)(sWl + n * QF_ROWB + kb);
                    fWl[nf][1] = *(const uint32_t*)(sWl + n * QF_ROWB + kb + 16);
                }
                #pragma unroll
                for (int mf = 0; mf < 4; mf++)
                    #pragma unroll
                    for (int nf = 0; nf < 4; nf++)
                        mma_f16(acc[mf][nf], fAh[mf][0], fAh[mf][1], fAh[mf][2],
                                fAh[mf][3], fWl[nf][0], fWl[nf][1]);
            }
        }
        __syncthreads();
        if (c + 2 < QF_CHUNKS) load_chunk(c + 2, s);
    }

    // ---- epilogue ----
    #pragma unroll
    for (int mf = 0; mf < 4; mf++) {
        int r0 = m0 + wm + mf * 16 + gp;
        #pragma unroll
        for (int nf = 0; nf < 4; nf++) {
            int col = n0 + wn + nf * 8 + 2 * tg;
            float b0 = bias[col], b1 = bias[col + 1];
            float v00 = acc[mf][nf][0] + b0, v01 = acc[mf][nf][1] + b1;
            float v10 = acc[mf][nf][2] + b0, v11 = acc[mf][nf][3] + b1;
            if (wf32) {
                *(float2*)(C + (size_t)r0 * TD + col)       = make_float2(v00, v01);
                *(float2*)(C + (size_t)(r0 + 8) * TD + col) = make_float2(v10, v11);
            }
            if (wf16) {
                __half h0, l0, h1, l1;
                f16_split(v00, h0, l0); f16_split(v01, h1, l1);
                *(__half2*)(Ch + (size_t)r0 * TD + col) = __halves2half2(h0, h1);
                *(__half2*)(Cl + (size_t)r0 * TD + col) = __halves2half2(l0, l1);
                f16_split(v10, h0, l0); f16_split(v11, h1, l1);
                *(__half2*)(Ch + (size_t)(r0 + 8) * TD + col) = __halves2half2(h0, h1);
                *(__half2*)(Cl + (size_t)(r0 + 8) * TD + col) = __halves2half2(l0, l1);
            }
        }
    }
}

// ---------------- row mask: rm[h][l] = sum_e mask[h,e,l] -------------------
__global__ void rowmask_kernel(const float* __restrict__ mask, float* __restrict__ rm)
{
    int h = blockIdx.x, l = threadIdx.x;
    float s = 0.f;
    for (int e = 0; e < EE; e++) s += mask[((size_t)h * EE + e) * LL + l];
    rm[h * LL + l] = s;
}

// ======== rowscore 3xFP16 mma: S_h[i,j] = sum_{s,c} Q[s,i,h,c] K[s,j,h,c] ==
// 128x128 tile per CTA, k-chunks of 32 over (s in ks*16..+16, c0 in {0,32}).
// grid (2 j-tiles, 2 i-tiles, h*8+ks), 256 thr, smem layout identical to qkv.
#define RS_CHUNKS 32

__global__ __launch_bounds__(256) void rowscore_mma(const __half* __restrict__ Qh,
                                                    const __half* __restrict__ Ql,
                                                    float* __restrict__ spart)
{
    extern __shared__ __align__(16) char smc[];
    uint32_t sb = smem_u32(smc);

    int tid = threadIdx.x;
    int wid = tid >> 5, lane = tid & 31;
    int gp = lane >> 2, tg = lane & 3;
    int wm = (wid & 1) * 64;
    int wn = (wid >> 1) * 32;
    int j0 = blockIdx.x * 128;
    int i0 = blockIdx.y * 128;
    int h  = blockIdx.z >> 3;
    int ks = blockIdx.z & 7;
    int ks16 = ks * 16;

    float acc[4][4][4];
    #pragma unroll
    for (int i = 0; i < 4; i++)
        #pragma unroll
        for (int j = 0; j < 4; j++)
            #pragma unroll
            for (int r = 0; r < 4; r++) acc[i][j][r] = 0.f;

    auto load_chunk = [&](int c, int stage) {
        int s  = ks16 + (c >> 1);
        int c0 = (c & 1) * 32;
        uint32_t base = sb + (uint32_t)(stage * QF_STAGEB);
        size_t gbase = (size_t)s * LL * TD + h * DHH + c0;
        #pragma unroll
        for (int i = 0; i < 8; i++) {
            int idx = tid + i * 256;
            int t4   = idx >> 9;               // 0=Ah 1=Al 2=Bh(K) 3=Bl(K)
            int r    = (idx >> 2) & 127;
            int seg  = idx & 3;
            int grow = (t4 < 2 ? i0 : j0) + r;
            size_t goff = gbase + (size_t)grow * TD + ((t4 >= 2) ? DD : 0) + seg * 8;
            const __half* src = (t4 & 1) ? Ql : Qh;
            uint32_t dst = base + (uint32_t)(t4 * QF_TILEB + r * QF_ROWB + seg * 16);
            cp_async16(dst, src + goff);
        }
        CP_COMMIT();
    };

    load_chunk(0, 0);
    load_chunk(1, 1);

    for (int c = 0; c < RS_CHUNKS; c++) {
        int s = c & 1;
        CP_WAIT1();
        __syncthreads();
        const char* stg = smc + s * QF_STAGEB;
        const char* sAh = stg;
        const char* sAl = stg + QF_TILEB;
        const char* sBh = stg + 2 * QF_TILEB;
        const char* sBl = stg + 3 * QF_TILEB;

        #pragma unroll
        for (int kss = 0; kss < 2; kss++) {
            int kb = (kss * 16 + 2 * tg) * 2;
            uint32_t fAh[4][4];
            #pragma unroll
            for (int mf = 0; mf < 4; mf++) {
                int r = wm + mf * 16 + gp;
                fAh[mf][0] = *(const uint32_t*)(sAh + r * QF_ROWB + kb);
                fAh[mf][1] = *(const uint32_t*)(sAh + (r + 8) * QF_ROWB + kb);
                fAh[mf][2] = *(const uint32_t*)(sAh + r * QF_ROWB + kb + 16);
                fAh[mf][3] = *(const uint32_t*)(sAh + (r + 8) * QF_ROWB + kb + 16);
            }
            uint32_t fBh[4][2];
            #pragma unroll
            for (int nf = 0; nf < 4; nf++) {
                int n = wn + nf * 8 + gp;
                fBh[nf][0] = *(const uint32_t*)(sBh + n * QF_ROWB + kb);
                fBh[nf][1] = *(const uint32_t*)(sBh + n * QF_ROWB + kb + 16);
            }
            #pragma unroll
            for (int mf = 0; mf < 4; mf++)
                #pragma unroll
                for (int nf = 0; nf < 4; nf++)
                    mma_f16(acc[mf][nf], fAh[mf][0], fAh[mf][1], fAh[mf][2],
                            fAh[mf][3], fBh[nf][0], fBh[nf][1]);
            {
                uint32_t fAl[4][4];
                #pragma unroll
                for (int mf = 0; mf < 4; mf++) {
                    int r = wm + mf * 16 + gp;
                    fAl[mf][0] = *(const uint32_t*)(sAl + r * QF_ROWB + kb);
                    fAl[mf][1] = *(const uint32_t*)(sAl + (r + 8) * QF_ROWB + kb);
                    fAl[mf][2] = *(const uint32_t*)(sAl + r * QF_ROWB + kb + 16);
                    fAl[mf][3] = *(const uint32_t*)(sAl + (r + 8) * QF_ROWB + kb + 16);
                }
                #pragma unroll
                for (int mf = 0; mf < 4; mf++)
                    #pragma unroll
                    for (int nf = 0; nf < 4; nf++)
                        mma_f16(acc[mf][nf], fAl[mf][0], fAl[mf][1], fAl[mf][2],
                                fAl[mf][3], fBh[nf][0], fBh[nf][1]);
            }
            {
                uint32_t fBl[4][2];
                #pragma unroll
                for (int nf = 0; nf < 4; nf++) {
                    int n = wn + nf * 8 + gp;
                    fBl[nf][0] = *(const uint32_t*)(sBl + n * QF_ROWB + kb);
                    fBl[nf][1] = *(const uint32_t*)(sBl + n * QF_ROWB + kb + 16);
                }
                #pragma unroll
                for (int mf = 0; mf < 4; mf++)
                    #pragma unroll
                    for (int nf = 0; nf < 4; nf++)
                        mma_f16(acc[mf][nf], fAh[mf][0], fAh[mf][1], fAh[mf][2],
                                fAh[mf][3], fBl[nf][0], fBl[nf][1]);
            }
        }
        __syncthreads();
        if (c + 2 < RS_CHUNKS) load_chunk(c + 2, s);
    }

    float* outp = spart + (size_t)(ks * HH + h) * (LL * LL);
    #pragma unroll
    for (int mf = 0; mf < 4; mf++) {
        int r0 = i0 + wm + mf * 16 + gp;
        #pragma unroll
        for (int nf = 0; nf < 4; nf++) {
            int col = j0 + wn + nf * 8 + 2 * tg;
            *(float2*)(outp + (size_t)r0 * LL + col) =
                make_float2(acc[mf][nf][0], acc[mf][nf][1]);
            *(float2*)(outp + (size_t)(r0 + 8) * LL + col) =
                make_float2(acc[mf][nf][2], acc[mf][nf][3]);
        }
    }
}

// ---------------- row softmax ----------------------------------------------
__global__ void rowsoftmax_kernel(const float* __restrict__ spart,
                                  const float* __restrict__ rm,
                                  float* __restrict__ maps)
{
    int i = blockIdx.x, h = blockIdx.y, j = threadIdx.x;
    size_t idx = ((size_t)h * LL + i) * LL + j;
    float v = rm[h * LL + j];
    #pragma unroll
    for (int p = 0; p < 8; p++) v += spart[(size_t)p * (HH * (size_t)LL * LL) + idx];
    __shared__ float r1[8], r2[8];
    float m = v;
    #pragma unroll
    for (int o = 16; o > 0; o >>= 1) m = fmaxf(m, __shfl_xor_sync(0xffffffffu, m, o));
    if ((j & 31) == 0) r1[j >> 5] = m;
    __syncthreads();
    m = r1[0];
    #pragma unroll
    for (int w = 1; w < 8; w++) m = fmaxf(m, r1[w]);
    float e = __expf(v - m);
    float s = e;
    #pragma unroll
    for (int o = 16; o > 0; o >>= 1) s += __shfl_xor_sync(0xffffffffu, s, o);
    if ((j & 31) == 0) r2[j >> 5] = s;
    __syncthreads();
    s = 0.f;
    #pragma unroll
    for (int w = 0; w < 8; w++) s += r2[w];
    maps[idx] = e / s;
}

// ---------------- row out: x1 = x + maps_h @ V_h (V from h/l fp16) ---------
__global__ __launch_bounds__(64) void rowout_kernel(const float* __restrict__ maps,
                                                    const __half* __restrict__ Vh,
                                                    const __half* __restrict__ Vl,
                                                    const float* __restrict__ xin,
                                                    float* __restrict__ xout)
{
    __shared__ float As[16][64];
    __shared__ float Bs[16][64];
    int h = blockIdx.z, s = blockIdx.y, i0 = blockIdx.x * 64;
    int t = threadIdx.x, ty = t >> 3, tx = t & 7;
    float acc[8][8] = {};
    const float* arow = maps + (size_t)(h * LL + i0 + t) * LL;

    for (int k0 = 0; k0 < LL; k0 += 16) {
        #pragma unroll
        for (int q = 0; q < 4; q++) {
            float4 a = *(const float4*)(arow + k0 + q * 4);
            As[q*4+0][t]=a.x; As[q*4+1][t]=a.y; As[q*4+2][t]=a.z; As[q*4+3][t]=a.w;
        }
        #pragma unroll
        for (int q = 0; q < 4; q++) {
            int f4 = t * 4 + q;
            int j  = f4 >> 4, c4 = f4 & 15;
            size_t src = (size_t)(s * LL + k0 + j) * TD + 2 * DD + h * DHH + c4 * 4;
            float2 h0 = __half22float2(*(const __half2*)(Vh + src));
            float2 h1 = __half22float2(*(const __half2*)(Vh + src + 2));
            float2 l0 = __half22float2(*(const __half2*)(Vl + src));
            float2 l1 = __half22float2(*(const __half2*)(Vl + src + 2));
            Bs[j][c4*4+0] = h0.x + l0.x;
            Bs[j][c4*4+1] = h0.y + l0.y;
            Bs[j][c4*4+2] = h1.x + l1.x;
            Bs[j][c4*4+3] = h1.y + l1.y;
        }
        __syncthreads();
        #pragma unroll
        for (int k = 0; k < 16; k++) {
            float a[8], b[8];
            *(float4*)(a)   = *(const float4*)&As[k][ty*8];
            *(float4*)(a+4) = *(const float4*)&As[k][ty*8+4];
            *(float4*)(b)   = *(const float4*)&Bs[k][tx*8];
            *(float4*)(b+4) = *(const float4*)&Bs[k][tx*8+4];
            #pragma unroll
            for (int u = 0; u < 8; u++)
                #pragma unroll
                for (int v = 0; v < 8; v++) acc[u][v] += a[u] * b[v];
        }
        __syncthreads();
    }
    #pragma unroll
    for (int u = 0; u < 8; u++) {
        int i = i0 + ty * 8 + u;
        size_t base = (size_t)(s * LL + i) * DD + h * DHH + tx * 8;
        #pragma unroll
        for (int v2 = 0; v2 < 8; v2 += 4) {
            float4 xi = *(const float4*)(xin + base + v2);
            float4 o;
            o.x = xi.x + acc[u][v2+0]; o.y = xi.y + acc[u][v2+1];
            o.z = xi.z + acc[u][v2+2]; o.w = xi.w + acc[u][v2+3];
            *(float4*)(xout + base + v2) = o;
        }
    }
}

// ---------------- fused column attention -----------------------------------
#define STQ 132
#define STV 68
#define COL_SMEM_BYTES ((128*STQ + 128*STV + 128) * 4)

__global__ __launch_bounds__(256) void colfused_kernel(const float* __restrict__ qkv,
                                                       const float* __restrict__ mask,
                                                       const float* __restrict__ xin,
                                                       float* __restrict__ out)
{
    extern __shared__ float cs[];
    float* QT = cs;
    float* KT = cs + 64 * STQ;
    float* ST = cs;
    float* Vs = cs + 128 * STQ;
    float* mk = Vs + 128 * STV;
    int l = blockIdx.x, h = blockIdx.y;
    int t = threadIdx.x;

    {
        int j = t >> 1, half = t & 1;
        const float* base = qkv + (size_t)(j * LL + l) * TD + h * DHH + half * 32;
        #pragma unroll
        for (int q = 0; q < 8; q++) {
            int c = half * 32 + q * 4;
            float4 qv = *(const float4*)(base + q * 4);
            float4 kv = *(const float4*)(base + DD + q * 4);
            float4 vv = *(const float4*)(base + 2 * DD + q * 4);
            QT[(c+0)*STQ + j] = qv.x; QT[(c+1)*STQ + j] = qv.y;
            QT[(c+2)*STQ + j] = qv.z; QT[(c+3)*STQ + j] = qv.w;
            KT[(c+0)*STQ + j] = kv.x; KT[(c+1)*STQ + j] = kv.y;
            KT[(c+2)*STQ + j] = kv.z; KT[(c+3)*STQ + j] = kv.w;
            *(float4*)&Vs[j * STV + c] = vv;
        }
        if (t < EE) mk[t] = mask[((size_t)h * EE + t) * LL + l];
    }
    __syncthreads();

    int ty = t >> 4, tx = t & 15;
    float accS[8][8] = {};
    #pragma unroll 4
    for (int c = 0; c < DHH; c++) {
        float a[8], b[8];
        *(float4*)(a)   = *(const float4*)&QT[c*STQ + ty*8];
        *(float4*)(a+4) = *(const float4*)&QT[c*STQ + ty*8+4];
        *(float4*)(b)   = *(const float4*)&KT[c*STQ + tx*8];
        *(float4*)(b+4) = *(const float4*)&KT[c*STQ + tx*8+4];
        #pragma unroll
        for (int u = 0; u < 8; u++)
            #pragma unroll
            for (int v = 0; v < 8; v++) accS[u][v] += a[u] * b[v];
    }
    __syncthreads();
    #pragma unroll
    for (int u = 0; u < 8; u++)
        #pragma unroll
        for (int v = 0; v < 8; v++)
            ST[(tx*8 + v) * STQ + (ty*8 + u)] = accS[u][v];
    __syncthreads();

    {
        int i = t >> 1, half = t & 1;
        float m = -1e30f;
        for (int tt = 0; tt < 64; tt++) {
            int j = half * 64 + tt;
            m = fmaxf(m, ST[j*STQ + i] + mk[j]);
        }
        m = fmaxf(m, __shfl_xor_sync(0xffffffffu, m, 1));
        float ssum = 0.f;
        for (int tt = 0; tt < 64; tt++) {
            int j = half * 64 + tt;
            float e = __expf(ST[j*STQ + i] + mk[j] - m);
            ST[j*STQ + i] = e;
            ssum += e;
        }
        ssum += __shfl_xor_sync(0xffffffffu, ssum, 1);
        float inv = 1.f / ssum;
        for (int tt = 0; tt < 64; tt++) {
            int j = half * 64 + tt;
            ST[j*STQ + i] *= inv;
        }
    }
    __syncthreads();

    {
        int ti = t >> 4, tc = t & 15;
        float accO[8][4] = {};
        for (int j = 0; j < EE; j++) {
            float p[8];
            *(float4*)(p)   = *(const float4*)&ST[j*STQ + ti*8];
            *(float4*)(p+4) = *(const float4*)&ST[j*STQ + ti*8+4];
            float4 vv = *(const float4*)&Vs[j*STV + tc*4];
            #pragma unroll
            for (int u = 0; u < 8; u++) {
                accO[u][0] += p[u] * vv.x; accO[u][1] += p[u] * vv.y;
                accO[u][2] += p[u] * vv.z; accO[u][3] += p[u] * vv.w;
            }
        }
        #pragma unroll
        for (int u = 0; u < 8; u++) {
            int i = ti * 8 + u;
            size_t base = (size_t)(i * LL + l) * DD + h * DHH + tc * 4;
            float4 xi = *(const float4*)(xin + base);
            float4 o;
            o.x = xi.x + accO[u][0]; o.y = xi.y + accO[u][1];
            o.z = xi.z + accO[u][2]; o.w = xi.w + accO[u][3];
            *(float4*)(out + base) = o;
        }
    }
}

// ---------------- launch ---------------------------------------------------
extern "C" void kernel_launch(void* const* d_in, const int* in_sizes, int n_in,
                              void* d_out, int out_size)
{
    const float* x     = (const float*)d_in[0];
    const float* mask  = (const float*)d_in[1];
    const float* w_row = (const float*)d_in[2];
    const float* b_row = (const float*)d_in[3];
    const float* w_col = (const float*)d_in[4];
    const float* b_col = (const float*)d_in[5];
    const float* g1    = (const float*)d_in[6];
    const float* be1   = (const float*)d_in[7];
    const float* g2    = (const float*)d_in[8];
    const float* be2   = (const float*)d_in[9];
    float* out = (float*)d_out;

    __half *p_ah, *p_al, *p_wh, *p_wl, *p_qh, *p_ql;
    float *p_qkv, *p_x1, *p_spart, *p_maps, *p_rm;
    cudaGetSymbolAddress((void**)&p_ah,    g_ah);
    cudaGetSymbolAddress((void**)&p_al,    g_al);
    cudaGetSymbolAddress((void**)&p_wh,    g_wh);
    cudaGetSymbolAddress((void**)&p_wl,    g_wl);
    cudaGetSymbolAddress((void**)&p_qh,    g_qh);
    cudaGetSymbolAddress((void**)&p_ql,    g_ql);
    cudaGetSymbolAddress((void**)&p_qkv,   g_qkv);
    cudaGetSymbolAddress((void**)&p_x1,    g_x1);
    cudaGetSymbolAddress((void**)&p_spart, g_spart);
    cudaGetSymbolAddress((void**)&p_maps,  g_maps);
    cudaGetSymbolAddress((void**)&p_rm,    g_rm);

    cudaFuncSetAttribute(qkv_fp16,
                         cudaFuncAttributeMaxDynamicSharedMemorySize, QF_SMEMB);
    cudaFuncSetAttribute(rowscore_mma,
                         cudaFuncAttributeMaxDynamicSharedMemorySize, QF_SMEMB);
    cudaFuncSetAttribute(colfused_kernel,
                         cudaFuncAttributeMaxDynamicSharedMemorySize, COL_SMEM_BYTES);

    // ---- row attention (qkv in split fp16 only) ----
    ln_split_kernel<<<RR, 256>>>(x, g1, be1, p_ah, p_al);
    wsplit_kernel<<<TD, 256>>>(w_row, p_wh, p_wl);
    qkv_fp16<<<dim3(TD / 128, RR / 128), 256, QF_SMEMB>>>(
        p_ah, p_al, p_wh, p_wl, b_row, p_qkv, p_qh, p_ql, 0, 1);
    rowmask_kernel<<<HH, LL>>>(mask, p_rm);
    rowscore_mma<<<dim3(2, 2, HH * 8), 256, QF_SMEMB>>>(p_qh, p_ql, p_spart);
    rowsoftmax_kernel<<<dim3(LL, HH), LL>>>(p_spart, p_rm, p_maps);
    rowout_kernel<<<dim3(4, EE, HH), 64>>>(p_maps, p_qh, p_ql, x, p_x1);

    // ---- column attention (qkv in fp32 only) ----
    ln_split_kernel<<<RR, 256>>>(p_x1, g2, be2, p_ah, p_al);
    wsplit_kernel<<<TD, 256>>>(w_col, p_wh, p_wl);
    qkv_fp16<<<dim3(TD / 128, RR / 128), 256, QF_SMEMB>>>(
        p_ah, p_al, p_wh, p_wl, b_col, p_qkv, p_qh, p_ql, 1, 0);
    colfused_kernel<<<dim3(LL, HH), 256, COL_SMEM_BYTES>>>(p_qkv, mask, p_x1, out);
}

// round 13
// speedup vs baseline: 2.5630x; 1.1811x over previous
#include <cuda_runtime.h>
#include <cuda_fp16.h>
#include <cstdint>

// Problem constants
#define EE 128          // E (rows / MSA depth)
#define LL 256          // L (sequence length)
#define HH 12           // heads
#define DHH 64          // head dim
#define DD 768          // D = H*DH
#define TD 2304         // 3*D
#define RR (EE*LL)      // 32768 rows

// ---------------- scratch (device globals; no allocation allowed) ----------
__device__ __align__(256) __half g_ah [(size_t)RR * DD];           // LN out hi
__device__ __align__(256) __half g_al [(size_t)RR * DD];           // LN out lo
__device__ __align__(256) __half g_wh [(size_t)TD * DD];           // W hi
__device__ __align__(256) __half g_wl [(size_t)TD * DD];           // W lo
__device__ __align__(256) __half g_qh [(size_t)RR * TD];           // qkv hi (row phase)
__device__ __align__(256) __half g_ql [(size_t)RR * TD];           // qkv lo (row phase)
__device__ __align__(256) float g_qkv [(size_t)RR * TD];           // qkv fp32 (col phase)
__device__ __align__(256) float g_x1  [(size_t)RR * DD];           // x + row_out
__device__ __align__(256) float g_spart[(size_t)8 * HH * LL * LL]; // split-K partials
__device__ __align__(256) __half g_maps16[(size_t)HH * LL * LL];   // row maps (fp16)
__device__ __align__(256) float g_rm  [HH * LL];                   // row mask

// ============================ helpers ======================================
__device__ __forceinline__ uint32_t smem_u32(const void* p) {
    uint32_t a;
    asm("{ .reg .u64 t; cvta.to.shared.u64 t, %1; cvt.u32.u64 %0, t; }"
        : "=r"(a) : "l"(p));
    return a;
}
__device__ __forceinline__ void cp_async16(uint32_t dst, const void* src) {
    asm volatile("cp.async.cg.shared.global [%0], [%1], 16;\n"
                 :: "r"(dst), "l"(src) : "memory");
}
#define CP_COMMIT() asm volatile("cp.async.commit_group;" ::: "memory")
#define CP_WAIT1()  asm volatile("cp.async.wait_group 1;" ::: "memory")
#define CP_WAIT0()  asm volatile("cp.async.wait_group 0;" ::: "memory")

__device__ __forceinline__ void mma_f16(float* c, uint32_t a0, uint32_t a1,
                                        uint32_t a2, uint32_t a3,
                                        uint32_t b0, uint32_t b1) {
    asm volatile("mma.sync.aligned.m16n8k16.row.col.f32.f16.f16.f32 "
                 "{%0,%1,%2,%3}, {%4,%5,%6,%7}, {%8,%9}, {%0,%1,%2,%3};"
                 : "+f"(c[0]), "+f"(c[1]), "+f"(c[2]), "+f"(c[3])
                 : "r"(a0), "r"(a1), "r"(a2), "r"(a3), "r"(b0), "r"(b1));
}

// split fp32 -> fp16 hi + fp16 lo
__device__ __forceinline__ void f16_split(float x, __half& h, __half& l) {
    h = __float2half_rn(x);
    l = __float2half_rn(x - __half2float(h));
}

// ---------- LayerNorm + fp16 2-way split: one CTA (256 thr) per row --------
__global__ void ln_split_kernel(const float* __restrict__ xin, const float* __restrict__ g,
                                const float* __restrict__ b,
                                __half* __restrict__ yh, __half* __restrict__ yl)
{
    int row = blockIdx.x, t = threadIdx.x;
    const float* xr = xin + (size_t)row * DD;
    float v0 = xr[t], v1 = xr[t + 256], v2 = xr[t + 512];
    float s  = v0 + v1 + v2;
    float s2 = v0*v0 + v1*v1 + v2*v2;
    __shared__ float rs[8], rs2[8];
    #pragma unroll
    for (int o = 16; o > 0; o >>= 1) {
        s  += __shfl_xor_sync(0xffffffffu, s,  o);
        s2 += __shfl_xor_sync(0xffffffffu, s2, o);
    }
    if ((t & 31) == 0) { rs[t >> 5] = s; rs2[t >> 5] = s2; }
    __syncthreads();
    float ts = 0.f, ts2 = 0.f;
    #pragma unroll
    for (int w = 0; w < 8; w++) { ts += rs[w]; ts2 += rs2[w]; }
    float mu  = ts  * (1.0f / DD);
    float var = ts2 * (1.0f / DD) - mu * mu;
    float inv = rsqrtf(var + 1e-5f);
    __half* yhr = yh + (size_t)row * DD;
    __half* ylr = yl + (size_t)row * DD;
    #pragma unroll
    for (int q = 0; q < 3; q++) {
        int k = t + q * 256;
        float v = (q == 0) ? v0 : (q == 1) ? v1 : v2;
        float yv = (v - mu) * inv * g[k] + b[k];
        __half h, l;
        f16_split(yv, h, l);
        yhr[k] = h; ylr[k] = l;
    }
}

// ---------- weight fp16 split: W[2304,768] -> wh, wl -----------------------
__global__ void wsplit_kernel(const float* __restrict__ w,
                              __half* __restrict__ wh, __half* __restrict__ wl)
{
    int row = blockIdx.x, t = threadIdx.x;
    const float* wr = w + (size_t)row * DD;
    __half* hr = wh + (size_t)row * DD;
    __half* lr = wl + (size_t)row * DD;
    #pragma unroll
    for (int q = 0; q < 3; q++) {
        int k = t + q * 256;
        __half h, l;
        f16_split(wr[k], h, l);
        hr[k] = h; lr[k] = l;
    }
}

// ============ 3xFP16 QKV GEMM: C[R,2304] = A[R,768] W[2304,768]^T + bias ===
// V-blocks (blockIdx.x >= vstart) run single-pass (hh only): V enters output
// linearly, so the ~2.4e-4 absolute error is within budget.
#define QF_ROWB    80
#define QF_TILEB   (128 * QF_ROWB)
#define QF_STAGEB  (4 * QF_TILEB)
#define QF_SMEMB   (2 * QF_STAGEB)             // 81920 B
#define QF_CHUNKS  (DD / 32)                   // 24

__global__ __launch_bounds__(256) void qkv_fp16(const __half* __restrict__ Ah,
                                                const __half* __restrict__ Al,
                                                const __half* __restrict__ Wh,
                                                const __half* __restrict__ Wl,
                                                const float* __restrict__ bias,
                                                float* __restrict__ C,
                                                __half* __restrict__ Ch,
                                                __half* __restrict__ Cl,
                                                int wf32, int wf16, int vstart)
{
    extern __shared__ __align__(16) char smc[];
    uint32_t sb = smem_u32(smc);

    int tid = threadIdx.x;
    int wid = tid >> 5, lane = tid & 31;
    int gp = lane >> 2, tg = lane & 3;
    int wm = (wid & 1) * 64;
    int wn = (wid >> 1) * 32;
    int m0 = blockIdx.y * 128;
    int n0 = blockIdx.x * 128;
    bool full = (int)blockIdx.x < vstart;   // Q/K blocks: 3 passes; V: 1 pass

    float acc[4][4][4];
    #pragma unroll
    for (int i = 0; i < 4; i++)
        #pragma unroll
        for (int j = 0; j < 4; j++)
            #pragma unroll
            for (int r = 0; r < 4; r++) acc[i][j][r] = 0.f;

    const __half* gsrc[4] = {Ah, Al, Wh, Wl};

    auto load_chunk = [&](int c, int stage) {
        int k0 = c * 32;
        uint32_t base = sb + (uint32_t)(stage * QF_STAGEB);
        #pragma unroll
        for (int i = 0; i < 8; i++) {
            int idx = tid + i * 256;
            int t4   = idx >> 9;
            int r    = (idx >> 2) & 127;
            int seg  = idx & 3;
            int grow = (t4 < 2 ? m0 : n0) + r;
            uint32_t dst = base + (uint32_t)(t4 * QF_TILEB + r * QF_ROWB + seg * 16);
            cp_async16(dst, gsrc[t4] + (size_t)grow * DD + k0 + seg * 8);
        }
        CP_COMMIT();
    };

    load_chunk(0, 0);
    load_chunk(1, 1);

    for (int c = 0; c < QF_CHUNKS; c++) {
        int s = c & 1;
        CP_WAIT1();
        __syncthreads();
        const char* stg = smc + s * QF_STAGEB;
        const char* sAh = stg;
        const char* sAl = stg + QF_TILEB;
        const char* sWh = stg + 2 * QF_TILEB;
        const char* sWl = stg + 3 * QF_TILEB;

        #pragma unroll
        for (int ks = 0; ks < 2; ks++) {
            int kb = (ks * 16 + 2 * tg) * 2;
            uint32_t fAh[4][4];
            #pragma unroll
            for (int mf = 0; mf < 4; mf++) {
                int r = wm + mf * 16 + gp;
                fAh[mf][0] = *(const uint32_t*)(sAh + r * QF_ROWB + kb);
                fAh[mf][1] = *(const uint32_t*)(sAh + (r + 8) * QF_ROWB + kb);
                fAh[mf][2] = *(const uint32_t*)(sAh + r * QF_ROWB + kb + 16);
                fAh[mf][3] = *(const uint32_t*)(sAh + (r + 8) * QF_ROWB + kb + 16);
            }
            uint32_t fWh[4][2];
            #pragma unroll
            for (int nf = 0; nf < 4; nf++) {
                int n = wn + nf * 8 + gp;
                fWh[nf][0] = *(const uint32_t*)(sWh + n * QF_ROWB + kb);
                fWh[nf][1] = *(const uint32_t*)(sWh + n * QF_ROWB + kb + 16);
            }
            #pragma unroll
            for (int mf = 0; mf < 4; mf++)
                #pragma unroll
                for (int nf = 0; nf < 4; nf++)
                    mma_f16(acc[mf][nf], fAh[mf][0], fAh[mf][1], fAh[mf][2],
                            fAh[mf][3], fWh[nf][0], fWh[nf][1]);
            if (full) {
                uint32_t fAl[4][4];
                #pragma unroll
                for (int mf = 0; mf < 4; mf++) {
                    int r = wm + mf * 16 + gp;
                    fAl[mf][0] = *(const uint32_t*)(sAl + r * QF_ROWB + kb);
                    fAl[mf][1] = *(const uint32_t*)(sAl + (r + 8) * QF_ROWB + kb);
                    fAl[mf][2] = *(const uint32_t*)(sAl + r * QF_ROWB + kb + 16);
                    fAl[mf][3] = *(const uint32_t*)(sAl + (r + 8) * QF_ROWB + kb + 16);
                }
                #pragma unroll
                for (int mf = 0; mf < 4; mf++)
                    #pragma unroll
                    for (int nf = 0; nf < 4; nf++)
                        mma_f16(acc[mf][nf], fAl[mf][0], fAl[mf][1], fAl[mf][2],
                                fAl[mf][3], fWh[nf][0], fWh[nf][1]);
                uint32_t fWl[4][2];
                #pragma unroll
                for (int nf = 0; nf < 4; nf++) {
                    int n = wn + nf * 8 + gp;
                    fWl[nf][0] = *(const uint32_t*)(sWl + n * QF_ROWB + kb);
                    fWl[nf][1] = *(const uint32_t*)(sWl + n * QF_ROWB + kb + 16);
                }
                #pragma unroll
                for (int mf = 0; mf < 4; mf++)
                    #pragma unroll
                    for (int nf = 0; nf < 4; nf++)
                        mma_f16(acc[mf][nf], fAh[mf][0], fAh[mf][1], fAh[mf][2],
                                fAh[mf][3], fWl[nf][0], fWl[nf][1]);
            }
        }
        __syncthreads();
        if (c + 2 < QF_CHUNKS) load_chunk(c + 2, s);
    }

    // ---- epilogue ----
    #pragma unroll
    for (int mf = 0; mf < 4; mf++) {
        int r0 = m0 + wm + mf * 16 + gp;
        #pragma unroll
        for (int nf = 0; nf < 4; nf++) {
            int col = n0 + wn + nf * 8 + 2 * tg;
            float b0 = bias[col], b1 = bias[col + 1];
            float v00 = acc[mf][nf][0] + b0, v01 = acc[mf][nf][1] + b1;
            float v10 = acc[mf][nf][2] + b0, v11 = acc[mf][nf][3] + b1;
            if (wf32) {
                *(float2*)(C + (size_t)r0 * TD + col)       = make_float2(v00, v01);
                *(float2*)(C + (size_t)(r0 + 8) * TD + col) = make_float2(v10, v11);
            }
            if (wf16) {
                __half h0, l0, h1, l1;
                f16_split(v00, h0, l0); f16_split(v01, h1, l1);
                *(__half2*)(Ch + (size_t)r0 * TD + col) = __halves2half2(h0, h1);
                *(__half2*)(Cl + (size_t)r0 * TD + col) = __halves2half2(l0, l1);
                f16_split(v10, h0, l0); f16_split(v11, h1, l1);
                *(__half2*)(Ch + (size_t)(r0 + 8) * TD + col) = __halves2half2(h0, h1);
                *(__half2*)(Cl + (size_t)(r0 + 8) * TD + col) = __halves2half2(l0, l1);
            }
        }
    }
}

// ---------------- row mask: rm[h][l] = sum_e mask[h,e,l] -------------------
__global__ void rowmask_kernel(const float* __restrict__ mask, float* __restrict__ rm)
{
    int h = blockIdx.x, l = threadIdx.x;
    float s = 0.f;
    for (int e = 0; e < EE; e++) s += mask[((size_t)h * EE + e) * LL + l];
    rm[h * LL + l] = s;
}

// ======== rowscore 3xFP16 mma: S_h[i,j] = sum_{s,c} Q[s,i,h,c] K[s,j,h,c] ==
#define RS_CHUNKS 32

__global__ __launch_bounds__(256) void rowscore_mma(const __half* __restrict__ Qh,
                                                    const __half* __restrict__ Ql,
                                                    float* __restrict__ spart)
{
    extern __shared__ __align__(16) char smc[];
    uint32_t sb = smem_u32(smc);

    int tid = threadIdx.x;
    int wid = tid >> 5, lane = tid & 31;
    int gp = lane >> 2, tg = lane & 3;
    int wm = (wid & 1) * 64;
    int wn = (wid >> 1) * 32;
    int j0 = blockIdx.x * 128;
    int i0 = blockIdx.y * 128;
    int h  = blockIdx.z >> 3;
    int ks = blockIdx.z & 7;
    int ks16 = ks * 16;

    float acc[4][4][4];
    #pragma unroll
    for (int i = 0; i < 4; i++)
        #pragma unroll
        for (int j = 0; j < 4; j++)
            #pragma unroll
            for (int r = 0; r < 4; r++) acc[i][j][r] = 0.f;

    auto load_chunk = [&](int c, int stage) {
        int s  = ks16 + (c >> 1);
        int c0 = (c & 1) * 32;
        uint32_t base = sb + (uint32_t)(stage * QF_STAGEB);
        size_t gbase = (size_t)s * LL * TD + h * DHH + c0;
        #pragma unroll
        for (int i = 0; i < 8; i++) {
            int idx = tid + i * 256;
            int t4   = idx >> 9;               // 0=Ah 1=Al 2=Bh(K) 3=Bl(K)
            int r    = (idx >> 2) & 127;
            int seg  = idx & 3;
            int grow = (t4 < 2 ? i0 : j0) + r;
            size_t goff = gbase + (size_t)grow * TD + ((t4 >= 2) ? DD : 0) + seg * 8;
            const __half* src = (t4 & 1) ? Ql : Qh;
            uint32_t dst = base + (uint32_t)(t4 * QF_TILEB + r * QF_ROWB + seg * 16);
            cp_async16(dst, src + goff);
        }
        CP_COMMIT();
    };

    load_chunk(0, 0);
    load_chunk(1, 1);

    for (int c = 0; c < RS_CHUNKS; c++) {
        int s = c & 1;
        CP_WAIT1();
        __syncthreads();
        const char* stg = smc + s * QF_STAGEB;
        const char* sAh = stg;
        const char* sAl = stg + QF_TILEB;
        const char* sBh = stg + 2 * QF_TILEB;
        const char* sBl = stg + 3 * QF_TILEB;

        #pragma unroll
        for (int kss = 0; kss < 2; kss++) {
            int kb = (kss * 16 + 2 * tg) * 2;
            uint32_t fAh[4][4];
            #pragma unroll
            for (int mf = 0; mf < 4; mf++) {
                int r = wm + mf * 16 + gp;
                fAh[mf][0] = *(const uint32_t*)(sAh + r * QF_ROWB + kb);
                fAh[mf][1] = *(const uint32_t*)(sAh + (r + 8) * QF_ROWB + kb);
                fAh[mf][2] = *(const uint32_t*)(sAh + r * QF_ROWB + kb + 16);
                fAh[mf][3] = *(const uint32_t*)(sAh + (r + 8) * QF_ROWB + kb + 16);
            }
            uint32_t fBh[4][2];
            #pragma unroll
            for (int nf = 0; nf < 4; nf++) {
                int n = wn + nf * 8 + gp;
                fBh[nf][0] = *(const uint32_t*)(sBh + n * QF_ROWB + kb);
                fBh[nf][1] = *(const uint32_t*)(sBh + n * QF_ROWB + kb + 16);
            }
            #pragma unroll
            for (int mf = 0; mf < 4; mf++)
                #pragma unroll
                for (int nf = 0; nf < 4; nf++)
                    mma_f16(acc[mf][nf], fAh[mf][0], fAh[mf][1], fAh[mf][2],
                            fAh[mf][3], fBh[nf][0], fBh[nf][1]);
            {
                uint32_t fAl[4][4];
                #pragma unroll
                for (int mf = 0; mf < 4; mf++) {
                    int r = wm + mf * 16 + gp;
                    fAl[mf][0] = *(const uint32_t*)(sAl + r * QF_ROWB + kb);
                    fAl[mf][1] = *(const uint32_t*)(sAl + (r + 8) * QF_ROWB + kb);
                    fAl[mf][2] = *(const uint32_t*)(sAl + r * QF_ROWB + kb + 16);
                    fAl[mf][3] = *(const uint32_t*)(sAl + (r + 8) * QF_ROWB + kb + 16);
                }
                #pragma unroll
                for (int mf = 0; mf < 4; mf++)
                    #pragma unroll
                    for (int nf = 0; nf < 4; nf++)
                        mma_f16(acc[mf][nf], fAl[mf][0], fAl[mf][1], fAl[mf][2],
                                fAl[mf][3], fBh[nf][0], fBh[nf][1]);
            }
            {
                uint32_t fBl[4][2];
                #pragma unroll
                for (int nf = 0; nf < 4; nf++) {
                    int n = wn + nf * 8 + gp;
                    fBl[nf][0] = *(const uint32_t*)(sBl + n * QF_ROWB + kb);
                    fBl[nf][1] = *(const uint32_t*)(sBl + n * QF_ROWB + kb + 16);
                }
                #pragma unroll
                for (int mf = 0; mf < 4; mf++)
                    #pragma unroll
                    for (int nf = 0; nf < 4; nf++)
                        mma_f16(acc[mf][nf], fAh[mf][0], fAh[mf][1], fAh[mf][2],
                                fAh[mf][3], fBl[nf][0], fBl[nf][1]);
            }
        }
        __syncthreads();
        if (c + 2 < RS_CHUNKS) load_chunk(c + 2, s);
    }

    float* outp = spart + (size_t)(ks * HH + h) * (LL * LL);
    #pragma unroll
    for (int mf = 0; mf < 4; mf++) {
        int r0 = i0 + wm + mf * 16 + gp;
        #pragma unroll
        for (int nf = 0; nf < 4; nf++) {
            int col = j0 + wn + nf * 8 + 2 * tg;
            *(float2*)(outp + (size_t)r0 * LL + col) =
                make_float2(acc[mf][nf][0], acc[mf][nf][1]);
            *(float2*)(outp + (size_t)(r0 + 8) * LL + col) =
                make_float2(acc[mf][nf][2], acc[mf][nf][3]);
        }
    }
}

// ---------------- row softmax -> fp16 maps ---------------------------------
__global__ void rowsoftmax_kernel(const float* __restrict__ spart,
                                  const float* __restrict__ rm,
                                  __half* __restrict__ maps16)
{
    int i = blockIdx.x, h = blockIdx.y, j = threadIdx.x;
    size_t idx = ((size_t)h * LL + i) * LL + j;
    float v = rm[h * LL + j];
    #pragma unroll
    for (int p = 0; p < 8; p++) v += spart[(size_t)p * (HH * (size_t)LL * LL) + idx];
    __shared__ float r1[8], r2[8];
    float m = v;
    #pragma unroll
    for (int o = 16; o > 0; o >>= 1) m = fmaxf(m, __shfl_xor_sync(0xffffffffu, m, o));
    if ((j & 31) == 0) r1[j >> 5] = m;
    __syncthreads();
    m = r1[0];
    #pragma unroll
    for (int w = 1; w < 8; w++) m = fmaxf(m, r1[w]);
    float e = __expf(v - m);
    float s = e;
    #pragma unroll
    for (int o = 16; o > 0; o >>= 1) s += __shfl_xor_sync(0xffffffffu, s, o);
    if ((j & 31) == 0) r2[j >> 5] = s;
    __syncthreads();
    s = 0.f;
    #pragma unroll
    for (int w = 0; w < 8; w++) s += r2[w];
    maps16[idx] = __float2half_rn(e / s);
}

// ======== rowout fp16 mma: x1 = x + maps_h @ V_h (per h,s: 128x64x256) =====
// A = maps16[h][i][j] (fp16), B = V^T built in smem from Vh+Vl.
// smem: A rows 0..127, V^T rows 128..191; stride 264 halfs (528 B).
#define RO_STRIDE 264
#define RO_SMEMB  ((128 + 64) * RO_STRIDE * 2)   // 101376 B

__global__ __launch_bounds__(256) void rowout_mma(const __half* __restrict__ maps16,
                                                  const __half* __restrict__ Vh,
                                                  const __half* __restrict__ Vl,
                                                  const float* __restrict__ xin,
                                                  float* __restrict__ xout)
{
    extern __shared__ __align__(16) char smc[];
    __half* sm_h = (__half*)smc;
    uint32_t sb = smem_u32(smc);

    int tid = threadIdx.x;
    int wid = tid >> 5, lane = tid & 31;
    int gp = lane >> 2, tg = lane & 3;
    int wm = (wid & 1) * 64;
    int wn = (wid >> 1) * 16;
    int i0 = blockIdx.x * 128;
    int s  = blockIdx.y;
    int h  = blockIdx.z;

    // ---- load A (maps16 [128 x 256]) via cp.async ----
    {
        const __half* abase = maps16 + ((size_t)h * LL + i0) * LL;
        #pragma unroll
        for (int i = 0; i < 16; i++) {
            int idx = tid + i * 256;          // 0..4095
            int r = idx >> 5, seg = idx & 31;
            cp_async16(sb + (uint32_t)(r * (RO_STRIDE*2) + seg * 16),
                       abase + (size_t)r * LL + seg * 8);
        }
        CP_COMMIT();
    }

    // ---- load V and transpose into smem rows 128..191 ----
    {
        int jlane = tid >> 3, seg = tid & 7;
        #pragma unroll
        for (int jb = 0; jb < 8; jb++) {
            int j = jb * 32 + jlane;
            size_t src = ((size_t)(s * LL + j)) * TD + 2 * DD + h * DHH + seg * 8;
            uint4 vh = *(const uint4*)(Vh + src);
            uint4 vl = *(const uint4*)(Vl + src);
            const uint32_t* ph = (const uint32_t*)&vh;
            const uint32_t* pl = (const uint32_t*)&vl;
            #pragma unroll
            for (int q = 0; q < 4; q++) {
                __half2 v2 = __hadd2(*(const __half2*)&ph[q], *(const __half2*)&pl[q]);
                int c = seg * 8 + q * 2;
                sm_h[(128 + c)     * RO_STRIDE + j] = __low2half(v2);
                sm_h[(128 + c + 1) * RO_STRIDE + j] = __high2half(v2);
            }
        }
    }
    CP_WAIT0();
    __syncthreads();

    // ---- 16 k16 mma steps ----
    float acc[4][2][4];
    #pragma unroll
    for (int i = 0; i < 4; i++)
        #pragma unroll
        for (int j = 0; j < 2; j++)
            #pragma unroll
            for (int r = 0; r < 4; r++) acc[i][j][r] = 0.f;

    const char* sbp = (const char*)smc;
    #pragma unroll
    for (int kst = 0; kst < 16; kst++) {
        int kb = (kst * 16 + 2 * tg) * 2;
        uint32_t fA[4][4];
        #pragma unroll
        for (int mf = 0; mf < 4; mf++) {
            int r = wm + mf * 16 + gp;
            fA[mf][0] = *(const uint32_t*)(sbp + r * (RO_STRIDE*2) + kb);
            fA[mf][1] = *(const uint32_t*)(sbp + (r + 8) * (RO_STRIDE*2) + kb);
            fA[mf][2] = *(const uint32_t*)(sbp + r * (RO_STRIDE*2) + kb + 16);
            fA[mf][3] = *(const uint32_t*)(sbp + (r + 8) * (RO_STRIDE*2) + kb + 16);
        }
        uint32_t fB[2][2];
        #pragma unroll
        for (int nf = 0; nf < 2; nf++) {
            int n = wn + nf * 8 + gp;
            fB[nf][0] = *(const uint32_t*)(sbp + (128 + n) * (RO_STRIDE*2) + kb);
            fB[nf][1] = *(const uint32_t*)(sbp + (128 + n) * (RO_STRIDE*2) + kb + 16);
        }
        #pragma unroll
        for (int mf = 0; mf < 4; mf++)
            #pragma unroll
            for (int nf = 0; nf < 2; nf++)
                mma_f16(acc[mf][nf], fA[mf][0], fA[mf][1], fA[mf][2], fA[mf][3],
                        fB[nf][0], fB[nf][1]);
    }

    // ---- epilogue: x1 = x + out ----
    #pragma unroll
    for (int mf = 0; mf < 4; mf++) {
        int r0 = i0 + wm + mf * 16 + gp;
        #pragma unroll
        for (int nf = 0; nf < 2; nf++) {
            int c0 = wn + nf * 8 + 2 * tg;
            size_t b0 = (size_t)(s * LL + r0) * DD + h * DHH + c0;
            size_t b1 = (size_t)(s * LL + r0 + 8) * DD + h * DHH + c0;
            float2 x0 = *(const float2*)(xin + b0);
            float2 x1v = *(const float2*)(xin + b1);
            *(float2*)(xout + b0) = make_float2(x0.x + acc[mf][nf][0],
                                                x0.y + acc[mf][nf][1]);
            *(float2*)(xout + b1) = make_float2(x1v.x + acc[mf][nf][2],
                                                x1v.y + acc[mf][nf][3]);
        }
    }
}

// ---------------- fused column attention -----------------------------------
#define STQ 132
#define STV 68
#define COL_SMEM_BYTES ((128*STQ + 128*STV + 128) * 4)

__global__ __launch_bounds__(256) void colfused_kernel(const float* __restrict__ qkv,
                                                       const float* __restrict__ mask,
                                                       const float* __restrict__ xin,
                                                       float* __restrict__ out)
{
    extern __shared__ float cs[];
    float* QT = cs;
    float* KT = cs + 64 * STQ;
    float* ST = cs;
    float* Vs = cs + 128 * STQ;
    float* mk = Vs + 128 * STV;
    int l = blockIdx.x, h = blockIdx.y;
    int t = threadIdx.x;

    {
        int j = t >> 1, half = t & 1;
        const float* base = qkv + (size_t)(j * LL + l) * TD + h * DHH + half * 32;
        #pragma unroll
        for (int q = 0; q < 8; q++) {
            int c = half * 32 + q * 4;
            float4 qv = *(const float4*)(base + q * 4);
            float4 kv = *(const float4*)(base + DD + q * 4);
            float4 vv = *(const float4*)(base + 2 * DD + q * 4);
            QT[(c+0)*STQ + j] = qv.x; QT[(c+1)*STQ + j] = qv.y;
            QT[(c+2)*STQ + j] = qv.z; QT[(c+3)*STQ + j] = qv.w;
            KT[(c+0)*STQ + j] = kv.x; KT[(c+1)*STQ + j] = kv.y;
            KT[(c+2)*STQ + j] = kv.z; KT[(c+3)*STQ + j] = kv.w;
            *(float4*)&Vs[j * STV + c] = vv;
        }
        if (t < EE) mk[t] = mask[((size_t)h * EE + t) * LL + l];
    }
    __syncthreads();

    int ty = t >> 4, tx = t & 15;
    float accS[8][8] = {};
    #pragma unroll 4
    for (int c = 0; c < DHH; c++) {
        float a[8], b[8];
        *(float4*)(a)   = *(const float4*)&QT[c*STQ + ty*8];
        *(float4*)(a+4) = *(const float4*)&QT[c*STQ + ty*8+4];
        *(float4*)(b)   = *(const float4*)&KT[c*STQ + tx*8];
        *(float4*)(b+4) = *(const float4*)&KT[c*STQ + tx*8+4];
        #pragma unroll
        for (int u = 0; u < 8; u++)
            #pragma unroll
            for (int v = 0; v < 8; v++) accS[u][v] += a[u] * b[v];
    }
    __syncthreads();
    #pragma unroll
    for (int u = 0; u < 8; u++)
        #pragma unroll
        for (int v = 0; v < 8; v++)
            ST[(tx*8 + v) * STQ + (ty*8 + u)] = accS[u][v];
    __syncthreads();

    {
        int i = t >> 1, half = t & 1;
        float m = -1e30f;
        for (int tt = 0; tt < 64; tt++) {
            int j = half * 64 + tt;
            m = fmaxf(m, ST[j*STQ + i] + mk[j]);
        }
        m = fmaxf(m, __shfl_xor_sync(0xffffffffu, m, 1));
        float ssum = 0.f;
        for (int tt = 0; tt < 64; tt++) {
            int j = half * 64 + tt;
            float e = __expf(ST[j*STQ + i] + mk[j] - m);
            ST[j*STQ + i] = e;
            ssum += e;
        }
        ssum += __shfl_xor_sync(0xffffffffu, ssum, 1);
        float inv = 1.f / ssum;
        for (int tt = 0; tt < 64; tt++) {
            int j = half * 64 + tt;
            ST[j*STQ + i] *= inv;
        }
    }
    __syncthreads();

    {
        int ti = t >> 4, tc = t & 15;
        float accO[8][4] = {};
        for (int j = 0; j < EE; j++) {
            float p[8];
            *(float4*)(p)   = *(const float4*)&ST[j*STQ + ti*8];
            *(float4*)(p+4) = *(const float4*)&ST[j*STQ + ti*8+4];
            float4 vv = *(const float4*)&Vs[j*STV + tc*4];
            #pragma unroll
            for (int u = 0; u < 8; u++) {
                accO[u][0] += p[u] * vv.x; accO[u][1] += p[u] * vv.y;
                accO[u][2] += p[u] * vv.z; accO[u][3] += p[u] * vv.w;
            }
        }
        #pragma unroll
        for (int u = 0; u < 8; u++) {
            int i = ti * 8 + u;
            size_t base = (size_t)(i * LL + l) * DD + h * DHH + tc * 4;
            float4 xi = *(const float4*)(xin + base);
            float4 o;
            o.x = xi.x + accO[u][0]; o.y = xi.y + accO[u][1];
            o.z = xi.z + accO[u][2]; o.w = xi.w + accO[u][3];
            *(float4*)(out + base) = o;
        }
    }
}

// ---------------- launch ---------------------------------------------------
extern "C" void kernel_launch(void* const* d_in, const int* in_sizes, int n_in,
                              void* d_out, int out_size)
{
    const float* x     = (const float*)d_in[0];
    const float* mask  = (const float*)d_in[1];
    const float* w_row = (const float*)d_in[2];
    const float* b_row = (const float*)d_in[3];
    const float* w_col = (const float*)d_in[4];
    const float* b_col = (const float*)d_in[5];
    const float* g1    = (const float*)d_in[6];
    const float* be1   = (const float*)d_in[7];
    const float* g2    = (const float*)d_in[8];
    const float* be2   = (const float*)d_in[9];
    float* out = (float*)d_out;

    __half *p_ah, *p_al, *p_wh, *p_wl, *p_qh, *p_ql, *p_maps16;
    float *p_qkv, *p_x1, *p_spart, *p_rm;
    cudaGetSymbolAddress((void**)&p_ah,     g_ah);
    cudaGetSymbolAddress((void**)&p_al,     g_al);
    cudaGetSymbolAddress((void**)&p_wh,     g_wh);
    cudaGetSymbolAddress((void**)&p_wl,     g_wl);
    cudaGetSymbolAddress((void**)&p_qh,     g_qh);
    cudaGetSymbolAddress((void**)&p_ql,     g_ql);
    cudaGetSymbolAddress((void**)&p_maps16, g_maps16);
    cudaGetSymbolAddress((void**)&p_qkv,    g_qkv);
    cudaGetSymbolAddress((void**)&p_x1,     g_x1);
    cudaGetSymbolAddress((void**)&p_spart,  g_spart);
    cudaGetSymbolAddress((void**)&p_rm,     g_rm);

    cudaFuncSetAttribute(qkv_fp16,
                         cudaFuncAttributeMaxDynamicSharedMemorySize, QF_SMEMB);
    cudaFuncSetAttribute(rowscore_mma,
                         cudaFuncAttributeMaxDynamicSharedMemorySize, QF_SMEMB);
    cudaFuncSetAttribute(rowout_mma,
                         cudaFuncAttributeMaxDynamicSharedMemorySize, RO_SMEMB);
    cudaFuncSetAttribute(colfused_kernel,
                         cudaFuncAttributeMaxDynamicSharedMemorySize, COL_SMEM_BYTES);

    // ---- row attention (qkv in split fp16 only; V single-pass) ----
    ln_split_kernel<<<RR, 256>>>(x, g1, be1, p_ah, p_al);
    wsplit_kernel<<<TD, 256>>>(w_row, p_wh, p_wl);
    qkv_fp16<<<dim3(TD / 128, RR / 128), 256, QF_SMEMB>>>(
        p_ah, p_al, p_wh, p_wl, b_row, p_qkv, p_qh, p_ql, 0, 1, 12);
    rowmask_kernel<<<HH, LL>>>(mask, p_rm);
    rowscore_mma<<<dim3(2, 2, HH * 8), 256, QF_SMEMB>>>(p_qh, p_ql, p_spart);
    rowsoftmax_kernel<<<dim3(LL, HH), LL>>>(p_spart, p_rm, p_maps16);
    rowout_mma<<<dim3(2, EE, HH), 256, RO_SMEMB>>>(p_maps16, p_qh, p_ql, x, p_x1);

    // ---- column attention (qkv in fp32 only; V single-pass) ----
    ln_split_kernel<<<RR, 256>>>(p_x1, g2, be2, p_ah, p_al);
    wsplit_kernel<<<TD, 256>>>(w_col, p_wh, p_wl);
    qkv_fp16<<<dim3(TD / 128, RR / 128), 256, QF_SMEMB>>>(
        p_ah, p_al, p_wh, p_wl, b_col, p_qkv, p_qh, p_ql, 1, 0, 12);
    colfused_kernel<<<dim3(LL, HH), 256, COL_SMEM_BYTES>>>(p_qkv, mask, p_x1, out);
}

// round 14
// speedup vs baseline: 2.7401x; 1.0691x over previous
#include <cuda_runtime.h>
#include <cuda_fp16.h>
#include <cstdint>

// Problem constants
#define EE 128          // E (rows / MSA depth)
#define LL 256          // L (sequence length)
#define HH 12           // heads
#define DHH 64          // head dim
#define DD 768          // D = H*DH
#define TD 2304         // 3*D
#define RR (EE*LL)      // 32768 rows

// ---------------- scratch (device globals; no allocation allowed) ----------
__device__ __align__(256) __half g_ah [(size_t)RR * DD];           // LN out hi
__device__ __align__(256) __half g_al [(size_t)RR * DD];           // LN out lo
__device__ __align__(256) __half g_wh [(size_t)TD * DD];           // W hi
__device__ __align__(256) __half g_wl [(size_t)TD * DD];           // W lo
__device__ __align__(256) __half g_qh [(size_t)RR * TD];           // qkv hi
__device__ __align__(256) __half g_ql [(size_t)RR * TD];           // qkv lo
__device__ __align__(256) float g_x1  [(size_t)RR * DD];           // x + row_out
__device__ __align__(256) float g_spart[(size_t)8 * HH * LL * LL]; // split-K partials
__device__ __align__(256) __half g_maps16[(size_t)HH * LL * LL];   // row maps (fp16)
__device__ __align__(256) float g_rm  [HH * LL];                   // row mask

// ============================ helpers ======================================
__device__ __forceinline__ uint32_t smem_u32(const void* p) {
    uint32_t a;
    asm("{ .reg .u64 t; cvta.to.shared.u64 t, %1; cvt.u32.u64 %0, t; }"
        : "=r"(a) : "l"(p));
    return a;
}
__device__ __forceinline__ void cp_async16(uint32_t dst, const void* src) {
    asm volatile("cp.async.cg.shared.global [%0], [%1], 16;\n"
                 :: "r"(dst), "l"(src) : "memory");
}
#define CP_COMMIT() asm volatile("cp.async.commit_group;" ::: "memory")
#define CP_WAIT1()  asm volatile("cp.async.wait_group 1;" ::: "memory")
#define CP_WAIT0()  asm volatile("cp.async.wait_group 0;" ::: "memory")

__device__ __forceinline__ void mma_f16(float* c, uint32_t a0, uint32_t a1,
                                        uint32_t a2, uint32_t a3,
                                        uint32_t b0, uint32_t b1) {
    asm volatile("mma.sync.aligned.m16n8k16.row.col.f32.f16.f16.f32 "
                 "{%0,%1,%2,%3}, {%4,%5,%6,%7}, {%8,%9}, {%0,%1,%2,%3};"
                 : "+f"(c[0]), "+f"(c[1]), "+f"(c[2]), "+f"(c[3])
                 : "r"(a0), "r"(a1), "r"(a2), "r"(a3), "r"(b0), "r"(b1));
}

// split fp32 -> fp16 hi + fp16 lo
__device__ __forceinline__ void f16_split(float x, __half& h, __half& l) {
    h = __float2half_rn(x);
    l = __float2half_rn(x - __half2float(h));
}

// ---------- LayerNorm + fp16 2-way split: one CTA (256 thr) per row --------
__global__ void ln_split_kernel(const float* __restrict__ xin, const float* __restrict__ g,
                                const float* __restrict__ b,
                                __half* __restrict__ yh, __half* __restrict__ yl)
{
    int row = blockIdx.x, t = threadIdx.x;
    const float* xr = xin + (size_t)row * DD;
    float v0 = xr[t], v1 = xr[t + 256], v2 = xr[t + 512];
    float s  = v0 + v1 + v2;
    float s2 = v0*v0 + v1*v1 + v2*v2;
    __shared__ float rs[8], rs2[8];
    #pragma unroll
    for (int o = 16; o > 0; o >>= 1) {
        s  += __shfl_xor_sync(0xffffffffu, s,  o);
        s2 += __shfl_xor_sync(0xffffffffu, s2, o);
    }
    if ((t & 31) == 0) { rs[t >> 5] = s; rs2[t >> 5] = s2; }
    __syncthreads();
    float ts = 0.f, ts2 = 0.f;
    #pragma unroll
    for (int w = 0; w < 8; w++) { ts += rs[w]; ts2 += rs2[w]; }
    float mu  = ts  * (1.0f / DD);
    float var = ts2 * (1.0f / DD) - mu * mu;
    float inv = rsqrtf(var + 1e-5f);
    __half* yhr = yh + (size_t)row * DD;
    __half* ylr = yl + (size_t)row * DD;
    #pragma unroll
    for (int q = 0; q < 3; q++) {
        int k = t + q * 256;
        float v = (q == 0) ? v0 : (q == 1) ? v1 : v2;
        float yv = (v - mu) * inv * g[k] + b[k];
        __half h, l;
        f16_split(yv, h, l);
        yhr[k] = h; ylr[k] = l;
    }
}

// ---------- weight fp16 split: W[2304,768] -> wh, wl -----------------------
__global__ void wsplit_kernel(const float* __restrict__ w,
                              __half* __restrict__ wh, __half* __restrict__ wl)
{
    int row = blockIdx.x, t = threadIdx.x;
    const float* wr = w + (size_t)row * DD;
    __half* hr = wh + (size_t)row * DD;
    __half* lr = wl + (size_t)row * DD;
    #pragma unroll
    for (int q = 0; q < 3; q++) {
        int k = t + q * 256;
        __half h, l;
        f16_split(wr[k], h, l);
        hr[k] = h; lr[k] = l;
    }
}

// ============ 3xFP16 QKV GEMM -> fp16 h/l output ===========================
// V-blocks (blockIdx.x >= vstart) run single-pass (hh only).
#define QF_ROWB    80
#define QF_TILEB   (128 * QF_ROWB)
#define QF_STAGEB  (4 * QF_TILEB)
#define QF_SMEMB   (2 * QF_STAGEB)             // 81920 B
#define QF_CHUNKS  (DD / 32)                   // 24

__global__ __launch_bounds__(256) void qkv_fp16(const __half* __restrict__ Ah,
                                                const __half* __restrict__ Al,
                                                const __half* __restrict__ Wh,
                                                const __half* __restrict__ Wl,
                                                const float* __restrict__ bias,
                                                __half* __restrict__ Ch,
                                                __half* __restrict__ Cl,
                                                int vstart)
{
    extern __shared__ __align__(16) char smc[];
    uint32_t sb = smem_u32(smc);

    int tid = threadIdx.x;
    int wid = tid >> 5, lane = tid & 31;
    int gp = lane >> 2, tg = lane & 3;
    int wm = (wid & 1) * 64;
    int wn = (wid >> 1) * 32;
    int m0 = blockIdx.y * 128;
    int n0 = blockIdx.x * 128;
    bool full = (int)blockIdx.x < vstart;

    float acc[4][4][4];
    #pragma unroll
    for (int i = 0; i < 4; i++)
        #pragma unroll
        for (int j = 0; j < 4; j++)
            #pragma unroll
            for (int r = 0; r < 4; r++) acc[i][j][r] = 0.f;

    const __half* gsrc[4] = {Ah, Al, Wh, Wl};

    auto load_chunk = [&](int c, int stage) {
        int k0 = c * 32;
        uint32_t base = sb + (uint32_t)(stage * QF_STAGEB);
        #pragma unroll
        for (int i = 0; i < 8; i++) {
            int idx = tid + i * 256;
            int t4   = idx >> 9;
            int r    = (idx >> 2) & 127;
            int seg  = idx & 3;
            int grow = (t4 < 2 ? m0 : n0) + r;
            uint32_t dst = base + (uint32_t)(t4 * QF_TILEB + r * QF_ROWB + seg * 16);
            cp_async16(dst, gsrc[t4] + (size_t)grow * DD + k0 + seg * 8);
        }
        CP_COMMIT();
    };

    load_chunk(0, 0);
    load_chunk(1, 1);

    for (int c = 0; c < QF_CHUNKS; c++) {
        int s = c & 1;
        CP_WAIT1();
        __syncthreads();
        const char* stg = smc + s * QF_STAGEB;
        const char* sAh = stg;
        const char* sAl = stg + QF_TILEB;
        const char* sWh = stg + 2 * QF_TILEB;
        const char* sWl = stg + 3 * QF_TILEB;

        #pragma unroll
        for (int ks = 0; ks < 2; ks++) {
            int kb = (ks * 16 + 2 * tg) * 2;
            uint32_t fAh[4][4];
            #pragma unroll
            for (int mf = 0; mf < 4; mf++) {
                int r = wm + mf * 16 + gp;
                fAh[mf][0] = *(const uint32_t*)(sAh + r * QF_ROWB + kb);
                fAh[mf][1] = *(const uint32_t*)(sAh + (r + 8) * QF_ROWB + kb);
                fAh[mf][2] = *(const uint32_t*)(sAh + r * QF_ROWB + kb + 16);
                fAh[mf][3] = *(const uint32_t*)(sAh + (r + 8) * QF_ROWB + kb + 16);
            }
            uint32_t fWh[4][2];
            #pragma unroll
            for (int nf = 0; nf < 4; nf++) {
                int n = wn + nf * 8 + gp;
                fWh[nf][0] = *(const uint32_t*)(sWh + n * QF_ROWB + kb);
                fWh[nf][1] = *(const uint32_t*)(sWh + n * QF_ROWB + kb + 16);
            }
            #pragma unroll
            for (int mf = 0; mf < 4; mf++)
                #pragma unroll
                for (int nf = 0; nf < 4; nf++)
                    mma_f16(acc[mf][nf], fAh[mf][0], fAh[mf][1], fAh[mf][2],
                            fAh[mf][3], fWh[nf][0], fWh[nf][1]);
            if (full) {
                uint32_t fAl[4][4];
                #pragma unroll
                for (int mf = 0; mf < 4; mf++) {
                    int r = wm + mf * 16 + gp;
                    fAl[mf][0] = *(const uint32_t*)(sAl + r * QF_ROWB + kb);
                    fAl[mf][1] = *(const uint32_t*)(sAl + (r + 8) * QF_ROWB + kb);
                    fAl[mf][2] = *(const uint32_t*)(sAl + r * QF_ROWB + kb + 16);
                    fAl[mf][3] = *(const uint32_t*)(sAl + (r + 8) * QF_ROWB + kb + 16);
                }
                #pragma unroll
                for (int mf = 0; mf < 4; mf++)
                    #pragma unroll
                    for (int nf = 0; nf < 4; nf++)
                        mma_f16(acc[mf][nf], fAl[mf][0], fAl[mf][1], fAl[mf][2],
                                fAl[mf][3], fWh[nf][0], fWh[nf][1]);
                uint32_t fWl[4][2];
                #pragma unroll
                for (int nf = 0; nf < 4; nf++) {
                    int n = wn + nf * 8 + gp;
                    fWl[nf][0] = *(const uint32_t*)(sWl + n * QF_ROWB + kb);
                    fWl[nf][1] = *(const uint32_t*)(sWl + n * QF_ROWB + kb + 16);
                }
                #pragma unroll
                for (int mf = 0; mf < 4; mf++)
                    #pragma unroll
                    for (int nf = 0; nf < 4; nf++)
                        mma_f16(acc[mf][nf], fAh[mf][0], fAh[mf][1], fAh[mf][2],
                                fAh[mf][3], fWl[nf][0], fWl[nf][1]);
            }
        }
        __syncthreads();
        if (c + 2 < QF_CHUNKS) load_chunk(c + 2, s);
    }

    // ---- epilogue: fp16 h/l ----
    #pragma unroll
    for (int mf = 0; mf < 4; mf++) {
        int r0 = m0 + wm + mf * 16 + gp;
        #pragma unroll
        for (int nf = 0; nf < 4; nf++) {
            int col = n0 + wn + nf * 8 + 2 * tg;
            float b0 = bias[col], b1 = bias[col + 1];
            float v00 = acc[mf][nf][0] + b0, v01 = acc[mf][nf][1] + b1;
            float v10 = acc[mf][nf][2] + b0, v11 = acc[mf][nf][3] + b1;
            __half h0, l0, h1, l1;
            f16_split(v00, h0, l0); f16_split(v01, h1, l1);
            *(__half2*)(Ch + (size_t)r0 * TD + col) = __halves2half2(h0, h1);
            *(__half2*)(Cl + (size_t)r0 * TD + col) = __halves2half2(l0, l1);
            f16_split(v10, h0, l0); f16_split(v11, h1, l1);
            *(__half2*)(Ch + (size_t)(r0 + 8) * TD + col) = __halves2half2(h0, h1);
            *(__half2*)(Cl + (size_t)(r0 + 8) * TD + col) = __halves2half2(l0, l1);
        }
    }
}

// ---------------- row mask: rm[h][l] = sum_e mask[h,e,l] -------------------
__global__ void rowmask_kernel(const float* __restrict__ mask, float* __restrict__ rm)
{
    int h = blockIdx.x, l = threadIdx.x;
    float s = 0.f;
    for (int e = 0; e < EE; e++) s += mask[((size_t)h * EE + e) * LL + l];
    rm[h * LL + l] = s;
}

// ======== rowscore 3xFP16 mma ==============================================
#define RS_CHUNKS 32

__global__ __launch_bounds__(256) void rowscore_mma(const __half* __restrict__ Qh,
                                                    const __half* __restrict__ Ql,
                                                    float* __restrict__ spart)
{
    extern __shared__ __align__(16) char smc[];
    uint32_t sb = smem_u32(smc);

    int tid = threadIdx.x;
    int wid = tid >> 5, lane = tid & 31;
    int gp = lane >> 2, tg = lane & 3;
    int wm = (wid & 1) * 64;
    int wn = (wid >> 1) * 32;
    int j0 = blockIdx.x * 128;
    int i0 = blockIdx.y * 128;
    int h  = blockIdx.z >> 3;
    int ks = blockIdx.z & 7;
    int ks16 = ks * 16;

    float acc[4][4][4];
    #pragma unroll
    for (int i = 0; i < 4; i++)
        #pragma unroll
        for (int j = 0; j < 4; j++)
            #pragma unroll
            for (int r = 0; r < 4; r++) acc[i][j][r] = 0.f;

    auto load_chunk = [&](int c, int stage) {
        int s  = ks16 + (c >> 1);
        int c0 = (c & 1) * 32;
        uint32_t base = sb + (uint32_t)(stage * QF_STAGEB);
        size_t gbase = (size_t)s * LL * TD + h * DHH + c0;
        #pragma unroll
        for (int i = 0; i < 8; i++) {
            int idx = tid + i * 256;
            int t4   = idx >> 9;
            int r    = (idx >> 2) & 127;
            int seg  = idx & 3;
            int grow = (t4 < 2 ? i0 : j0) + r;
            size_t goff = gbase + (size_t)grow * TD + ((t4 >= 2) ? DD : 0) + seg * 8;
            const __half* src = (t4 & 1) ? Ql : Qh;
            uint32_t dst = base + (uint32_t)(t4 * QF_TILEB + r * QF_ROWB + seg * 16);
            cp_async16(dst, src + goff);
        }
        CP_COMMIT();
    };

    load_chunk(0, 0);
    load_chunk(1, 1);

    for (int c = 0; c < RS_CHUNKS; c++) {
        int s = c & 1;
        CP_WAIT1();
        __syncthreads();
        const char* stg = smc + s * QF_STAGEB;
        const char* sAh = stg;
        const char* sAl = stg + QF_TILEB;
        const char* sBh = stg + 2 * QF_TILEB;
        const char* sBl = stg + 3 * QF_TILEB;

        #pragma unroll
        for (int kss = 0; kss < 2; kss++) {
            int kb = (kss * 16 + 2 * tg) * 2;
            uint32_t fAh[4][4];
            #pragma unroll
            for (int mf = 0; mf < 4; mf++) {
                int r = wm + mf * 16 + gp;
                fAh[mf][0] = *(const uint32_t*)(sAh + r * QF_ROWB + kb);
                fAh[mf][1] = *(const uint32_t*)(sAh + (r + 8) * QF_ROWB + kb);
                fAh[mf][2] = *(const uint32_t*)(sAh + r * QF_ROWB + kb + 16);
                fAh[mf][3] = *(const uint32_t*)(sAh + (r + 8) * QF_ROWB + kb + 16);
            }
            uint32_t fBh[4][2];
            #pragma unroll
            for (int nf = 0; nf < 4; nf++) {
                int n = wn + nf * 8 + gp;
                fBh[nf][0] = *(const uint32_t*)(sBh + n * QF_ROWB + kb);
                fBh[nf][1] = *(const uint32_t*)(sBh + n * QF_ROWB + kb + 16);
            }
            #pragma unroll
            for (int mf = 0; mf < 4; mf++)
                #pragma unroll
                for (int nf = 0; nf < 4; nf++)
                    mma_f16(acc[mf][nf], fAh[mf][0], fAh[mf][1], fAh[mf][2],
                            fAh[mf][3], fBh[nf][0], fBh[nf][1]);
            {
                uint32_t fAl[4][4];
                #pragma unroll
                for (int mf = 0; mf < 4; mf++) {
                    int r = wm + mf * 16 + gp;
                    fAl[mf][0] = *(const uint32_t*)(sAl + r * QF_ROWB + kb);
                    fAl[mf][1] = *(const uint32_t*)(sAl + (r + 8) * QF_ROWB + kb);
                    fAl[mf][2] = *(const uint32_t*)(sAl + r * QF_ROWB + kb + 16);
                    fAl[mf][3] = *(const uint32_t*)(sAl + (r + 8) * QF_ROWB + kb + 16);
                }
                #pragma unroll
                for (int mf = 0; mf < 4; mf++)
                    #pragma unroll
                    for (int nf = 0; nf < 4; nf++)
                        mma_f16(acc[mf][nf], fAl[mf][0], fAl[mf][1], fAl[mf][2],
                                fAl[mf][3], fBh[nf][0], fBh[nf][1]);
            }
            {
                uint32_t fBl[4][2];
                #pragma unroll
                for (int nf = 0; nf < 4; nf++) {
                    int n = wn + nf * 8 + gp;
                    fBl[nf][0] = *(const uint32_t*)(sBl + n * QF_ROWB + kb);
                    fBl[nf][1] = *(const uint32_t*)(sBl + n * QF_ROWB + kb + 16);
                }
                #pragma unroll
                for (int mf = 0; mf < 4; mf++)
                    #pragma unroll
                    for (int nf = 0; nf < 4; nf++)
                        mma_f16(acc[mf][nf], fAh[mf][0], fAh[mf][1], fAh[mf][2],
                                fAh[mf][3], fBl[nf][0], fBl[nf][1]);
            }
        }
        __syncthreads();
        if (c + 2 < RS_CHUNKS) load_chunk(c + 2, s);
    }

    float* outp = spart + (size_t)(ks * HH + h) * (LL * LL);
    #pragma unroll
    for (int mf = 0; mf < 4; mf++) {
        int r0 = i0 + wm + mf * 16 + gp;
        #pragma unroll
        for (int nf = 0; nf < 4; nf++) {
            int col = j0 + wn + nf * 8 + 2 * tg;
            *(float2*)(outp + (size_t)r0 * LL + col) =
                make_float2(acc[mf][nf][0], acc[mf][nf][1]);
            *(float2*)(outp + (size_t)(r0 + 8) * LL + col) =
                make_float2(acc[mf][nf][2], acc[mf][nf][3]);
        }
    }
}

// ---------------- row softmax -> fp16 maps ---------------------------------
__global__ void rowsoftmax_kernel(const float* __restrict__ spart,
                                  const float* __restrict__ rm,
                                  __half* __restrict__ maps16)
{
    int i = blockIdx.x, h = blockIdx.y, j = threadIdx.x;
    size_t idx = ((size_t)h * LL + i) * LL + j;
    float v = rm[h * LL + j];
    #pragma unroll
    for (int p = 0; p < 8; p++) v += spart[(size_t)p * (HH * (size_t)LL * LL) + idx];
    __shared__ float r1[8], r2[8];
    float m = v;
    #pragma unroll
    for (int o = 16; o > 0; o >>= 1) m = fmaxf(m, __shfl_xor_sync(0xffffffffu, m, o));
    if ((j & 31) == 0) r1[j >> 5] = m;
    __syncthreads();
    m = r1[0];
    #pragma unroll
    for (int w = 1; w < 8; w++) m = fmaxf(m, r1[w]);
    float e = __expf(v - m);
    float s = e;
    #pragma unroll
    for (int o = 16; o > 0; o >>= 1) s += __shfl_xor_sync(0xffffffffu, s, o);
    if ((j & 31) == 0) r2[j >> 5] = s;
    __syncthreads();
    s = 0.f;
    #pragma unroll
    for (int w = 0; w < 8; w++) s += r2[w];
    maps16[idx] = __float2half_rn(e / s);
}

// ======== rowout fp16 mma: x1 = x + maps_h @ V  (2-pass Vh/Vl) =============
#define RO_STRIDE 264
#define RO_SMEMB  ((128 + 128) * RO_STRIDE * 2)   // 135168 B

__global__ __launch_bounds__(256) void rowout_mma(const __half* __restrict__ maps16,
                                                  const __half* __restrict__ Vh,
                                                  const __half* __restrict__ Vl,
                                                  const float* __restrict__ xin,
                                                  float* __restrict__ xout)
{
    extern __shared__ __align__(16) char smc[];
    __half* sm_h = (__half*)smc;
    uint32_t sb = smem_u32(smc);

    int tid = threadIdx.x;
    int wid = tid >> 5, lane = tid & 31;
    int gp = lane >> 2, tg = lane & 3;
    int wm = (wid & 1) * 64;
    int wn = (wid >> 1) * 16;
    int i0 = blockIdx.x * 128;
    int s  = blockIdx.y;
    int h  = blockIdx.z;

    // ---- load A (maps16 [128 x 256]) via cp.async ----
    {
        const __half* abase = maps16 + ((size_t)h * LL + i0) * LL;
        #pragma unroll
        for (int i = 0; i < 16; i++) {
            int idx = tid + i * 256;
            int r = idx >> 5, seg = idx & 31;
            cp_async16(sb + (uint32_t)(r * (RO_STRIDE*2) + seg * 16),
                       abase + (size_t)r * LL + seg * 8);
        }
        CP_COMMIT();
    }

    // ---- load V; Vh^T into rows 128..191, Vl^T into rows 192..255 ----
    {
        int jlane = tid >> 3, seg = tid & 7;
        #pragma unroll
        for (int jb = 0; jb < 8; jb++) {
            int j = jb * 32 + jlane;
            size_t src = ((size_t)(s * LL + j)) * TD + 2 * DD + h * DHH + seg * 8;
            uint4 vh = *(const uint4*)(Vh + src);
            uint4 vl = *(const uint4*)(Vl + src);
            const __half* ph = (const __half*)&vh;
            const __half* pl = (const __half*)&vl;
            #pragma unroll
            for (int q = 0; q < 8; q++) {
                int c = seg * 8 + q;
                sm_h[(128 + c) * RO_STRIDE + j] = ph[q];
                sm_h[(192 + c) * RO_STRIDE + j] = pl[q];
            }
        }
    }
    CP_WAIT0();
    __syncthreads();

    // ---- 16 k16 mma steps x 2 V passes ----
    float acc[4][2][4];
    #pragma unroll
    for (int i = 0; i < 4; i++)
        #pragma unroll
        for (int j = 0; j < 2; j++)
            #pragma unroll
            for (int r = 0; r < 4; r++) acc[i][j][r] = 0.f;

    const char* sbp = (const char*)smc;
    #pragma unroll
    for (int kst = 0; kst < 16; kst++) {
        int kb = (kst * 16 + 2 * tg) * 2;
        uint32_t fA[4][4];
        #pragma unroll
        for (int mf = 0; mf < 4; mf++) {
            int r = wm + mf * 16 + gp;
            fA[mf][0] = *(const uint32_t*)(sbp + r * (RO_STRIDE*2) + kb);
            fA[mf][1] = *(const uint32_t*)(sbp + (r + 8) * (RO_STRIDE*2) + kb);
            fA[mf][2] = *(const uint32_t*)(sbp + r * (RO_STRIDE*2) + kb + 16);
            fA[mf][3] = *(const uint32_t*)(sbp + (r + 8) * (RO_STRIDE*2) + kb + 16);
        }
        #pragma unroll
        for (int vp = 0; vp < 2; vp++) {
            uint32_t fB[2][2];
            int vbase = 128 + vp * 64;
            #pragma unroll
            for (int nf = 0; nf < 2; nf++) {
                int n = wn + nf * 8 + gp;
                fB[nf][0] = *(const uint32_t*)(sbp + (vbase + n) * (RO_STRIDE*2) + kb);
                fB[nf][1] = *(const uint32_t*)(sbp + (vbase + n) * (RO_STRIDE*2) + kb + 16);
            }
            #pragma unroll
            for (int mf = 0; mf < 4; mf++)
                #pragma unroll
                for (int nf = 0; nf < 2; nf++)
                    mma_f16(acc[mf][nf], fA[mf][0], fA[mf][1], fA[mf][2], fA[mf][3],
                            fB[nf][0], fB[nf][1]);
        }
    }

    // ---- epilogue: x1 = x + out ----
    #pragma unroll
    for (int mf = 0; mf < 4; mf++) {
        int r0 = i0 + wm + mf * 16 + gp;
        #pragma unroll
        for (int nf = 0; nf < 2; nf++) {
            int c0 = wn + nf * 8 + 2 * tg;
            size_t b0 = (size_t)(s * LL + r0) * DD + h * DHH + c0;
            size_t b1 = (size_t)(s * LL + r0 + 8) * DD + h * DHH + c0;
            float2 x0 = *(const float2*)(xin + b0);
            float2 x1v = *(const float2*)(xin + b1);
            *(float2*)(xout + b0) = make_float2(x0.x + acc[mf][nf][0],
                                                x0.y + acc[mf][nf][1]);
            *(float2*)(xout + b1) = make_float2(x1v.x + acc[mf][nf][2],
                                                x1v.y + acc[mf][nf][3]);
        }
    }
}

// ======== fused column attention, fp16 mma ================================
// Per (h,l): S[i][j] = 3xfp16(Q_i . K_j) (+mask[j]); softmax_j; out = P(Vh+Vl).
// Smem: QK tiles 4x[128][72]h (72KB, aliased by S fp32 [128][136] after use),
//       Vth/Vtl [64][136]h, P16 [128][136]h, mask[128]f.
#define CF_QKT   18432                       // 128*72*2
#define CF_VTH   73728
#define CF_VTL   (CF_VTH + 17408)
#define CF_P16   (CF_VTL + 17408)            // 108544
#define CF_MK    (CF_P16 + 34816)            // 143360
#define CF_SMEMB (CF_MK + 512)               // 143872

__global__ __launch_bounds__(256) void colfused_mma(const __half* __restrict__ Qh,
                                                    const __half* __restrict__ Ql,
                                                    const float* __restrict__ mask,
                                                    const float* __restrict__ xin,
                                                    float* __restrict__ out)
{
    extern __shared__ __align__(16) char smc[];
    __half* sm_h = (__half*)smc;
    float*  sm_f = (float*)smc;
    uint32_t sb = smem_u32(smc);

    int tid = threadIdx.x;
    int wid = tid >> 5, lane = tid & 31;
    int gp = lane >> 2, tg = lane & 3;
    int wm = (wid & 1) * 64;
    int wn = (wid >> 1) * 32;    // S-phase: n in 4x32
    int wn2 = (wid >> 1) * 16;   // PV-phase: n in 4x16
    int l = blockIdx.x, h = blockIdx.y;

    // ---- loads: Qh/Ql/Kh/Kl via cp.async (rows j, 64 halfs each) ----
    {
        #pragma unroll
        for (int i = 0; i < 16; i++) {
            int idx = tid + i * 256;            // 0..4095
            int t4  = idx >> 10;                // 0=Qh 1=Ql 2=Kh 3=Kl
            int r   = (idx >> 3) & 127;
            int seg = idx & 7;
            const __half* src = (t4 & 1) ? Ql : Qh;
            size_t goff = ((size_t)(r * LL + l)) * TD + ((t4 >= 2) ? DD : 0)
                        + h * DHH + seg * 8;
            cp_async16(sb + (uint32_t)(t4 * CF_QKT + r * 144 + seg * 16), src + goff);
        }
        CP_COMMIT();
    }
    // ---- V^T tiles (Vh, Vl) + mask ----
    {
        int jlane = tid >> 1, seg = tid & 1;    // 2 threads per row, 32 halfs each
        size_t src = ((size_t)(jlane * LL + l)) * TD + 2 * DD + h * DHH + seg * 32;
        #pragma unroll
        for (int q = 0; q < 4; q++) {
            uint4 vh = *(const uint4*)(Qh + src + q * 8);
            uint4 vl = *(const uint4*)(Ql + src + q * 8);
            const __half* ph = (const __half*)&vh;
            const __half* pl = (const __half*)&vl;
            #pragma unroll
            for (int qq = 0; qq < 8; qq++) {
                int c = seg * 32 + q * 8 + qq;
                sm_h[CF_VTH/2 + c * 136 + jlane] = ph[qq];
                sm_h[CF_VTL/2 + c * 136 + jlane] = pl[qq];
            }
        }
        if (tid < EE) sm_f[CF_MK/4 + tid] = mask[((size_t)h * EE + tid) * LL + l];
    }
    CP_WAIT0();
    __syncthreads();

    // ---- S = QK^T, 3 passes, k=64 (4 k16 steps) ----
    float acc[4][4][4];
    #pragma unroll
    for (int i = 0; i < 4; i++)
        #pragma unroll
        for (int j = 0; j < 4; j++)
            #pragma unroll
            for (int r = 0; r < 4; r++) acc[i][j][r] = 0.f;

    const char* sQh = smc;
    const char* sQl = smc + CF_QKT;
    const char* sKh = smc + 2 * CF_QKT;
    const char* sKl = smc + 3 * CF_QKT;

    #pragma unroll
    for (int kst = 0; kst < 4; kst++) {
        int kb = (kst * 16 + 2 * tg) * 2;
        uint32_t fQh[4][4], fQl[4][4];
        #pragma unroll
        for (int mf = 0; mf < 4; mf++) {
            int r = wm + mf * 16 + gp;
            fQh[mf][0] = *(const uint32_t*)(sQh + r * 144 + kb);
            fQh[mf][1] = *(const uint32_t*)(sQh + (r + 8) * 144 + kb);
            fQh[mf][2] = *(const uint32_t*)(sQh + r * 144 + kb + 16);
            fQh[mf][3] = *(const uint32_t*)(sQh + (r + 8) * 144 + kb + 16);
            fQl[mf][0] = *(const uint32_t*)(sQl + r * 144 + kb);
            fQl[mf][1] = *(const uint32_t*)(sQl + (r + 8) * 144 + kb);
            fQl[mf][2] = *(const uint32_t*)(sQl + r * 144 + kb + 16);
            fQl[mf][3] = *(const uint32_t*)(sQl + (r + 8) * 144 + kb + 16);
        }
        uint32_t fKh[4][2], fKl[4][2];
        #pragma unroll
        for (int nf = 0; nf < 4; nf++) {
            int n = wn + nf * 8 + gp;
            fKh[nf][0] = *(const uint32_t*)(sKh + n * 144 + kb);
            fKh[nf][1] = *(const uint32_t*)(sKh + n * 144 + kb + 16);
            fKl[nf][0] = *(const uint32_t*)(sKl + n * 144 + kb);
            fKl[nf][1] = *(const uint32_t*)(sKl + n * 144 + kb + 16);
        }
        #pragma unroll
        for (int mf = 0; mf < 4; mf++)
            #pragma unroll
            for (int nf = 0; nf < 4; nf++) {
                mma_f16(acc[mf][nf], fQh[mf][0], fQh[mf][1], fQh[mf][2], fQh[mf][3],
                        fKh[nf][0], fKh[nf][1]);
                mma_f16(acc[mf][nf], fQl[mf][0], fQl[mf][1], fQl[mf][2], fQl[mf][3],
                        fKh[nf][0], fKh[nf][1]);
                mma_f16(acc[mf][nf], fQh[mf][0], fQh[mf][1], fQh[mf][2], fQh[mf][3],
                        fKl[nf][0], fKl[nf][1]);
            }
    }
    __syncthreads();   // all QK reads done before S overwrites the region

    // ---- store S fp32 [i][j] stride 136 (aliases QK tiles) ----
    #pragma unroll
    for (int mf = 0; mf < 4; mf++) {
        int r0 = wm + mf * 16 + gp;
        #pragma unroll
        for (int nf = 0; nf < 4; nf++) {
            int col = wn + nf * 8 + 2 * tg;
            *(float2*)(sm_f + r0 * 136 + col) =
                make_float2(acc[mf][nf][0], acc[mf][nf][1]);
            *(float2*)(sm_f + (r0 + 8) * 136 + col) =
                make_float2(acc[mf][nf][2], acc[mf][nf][3]);
        }
    }
    __syncthreads();

    // ---- softmax over j; write P16 ----
    {
        int i = tid >> 1, half = tid & 1;
        const float* srow = sm_f + i * 136;
        const float* mk = sm_f + CF_MK/4;
        __half* prow = sm_h + CF_P16/2 + i * 136;
        float m = -1e30f;
        #pragma unroll 8
        for (int tt = 0; tt < 64; tt++) {
            int j = half * 64 + tt;
            m = fmaxf(m, srow[j] + mk[j]);
        }
        m = fmaxf(m, __shfl_xor_sync(0xffffffffu, m, 1));
        float ssum = 0.f;
        float ev[64];
        #pragma unroll 8
        for (int tt = 0; tt < 64; tt++) {
            int j = half * 64 + tt;
            float e = __expf(srow[j] + mk[j] - m);
            ev[tt] = e;
            ssum += e;
        }
        ssum += __shfl_xor_sync(0xffffffffu, ssum, 1);
        float inv = 1.f / ssum;
        #pragma unroll 8
        for (int tt = 0; tt < 64; tt++) {
            int j = half * 64 + tt;
            prow[j] = __float2half_rn(ev[tt] * inv);
        }
    }
    __syncthreads();

    // ---- PV: out = P (Vh + Vl), k=128 (8 k16 steps), 2 B passes ----
    float acc2[4][2][4];
    #pragma unroll
    for (int i = 0; i < 4; i++)
        #pragma unroll
        for (int j = 0; j < 2; j++)
            #pragma unroll
            for (int r = 0; r < 4; r++) acc2[i][j][r] = 0.f;

    const char* sP  = smc + CF_P16;
    #pragma unroll
    for (int kst = 0; kst < 8; kst++) {
        int kb = (kst * 16 + 2 * tg) * 2;
        uint32_t fA[4][4];
        #pragma unroll
        for (int mf = 0; mf < 4; mf++) {
            int r = wm + mf * 16 + gp;
            fA[mf][0] = *(const uint32_t*)(sP + r * 272 + kb);
            fA[mf][1] = *(const uint32_t*)(sP + (r + 8) * 272 + kb);
            fA[mf][2] = *(const uint32_t*)(sP + r * 272 + kb + 16);
            fA[mf][3] = *(const uint32_t*)(sP + (r + 8) * 272 + kb + 16);
        }
        #pragma unroll
        for (int vp = 0; vp < 2; vp++) {
            const char* sVt = smc + (vp ? CF_VTL : CF_VTH);
            uint32_t fB[2][2];
            #pragma unroll
            for (int nf = 0; nf < 2; nf++) {
                int n = wn2 + nf * 8 + gp;
                fB[nf][0] = *(const uint32_t*)(sVt + n * 272 + kb);
                fB[nf][1] = *(const uint32_t*)(sVt + n * 272 + kb + 16);
            }
            #pragma unroll
            for (int mf = 0; mf < 4; mf++)
                #pragma unroll
                for (int nf = 0; nf < 2; nf++)
                    mma_f16(acc2[mf][nf], fA[mf][0], fA[mf][1], fA[mf][2], fA[mf][3],
                            fB[nf][0], fB[nf][1]);
        }
    }

    // ---- epilogue: out = x1 + PV ----
    #pragma unroll
    for (int mf = 0; mf < 4; mf++) {
        int i0 = wm + mf * 16 + gp;
        #pragma unroll
        for (int nf = 0; nf < 2; nf++) {
            int c0 = wn2 + nf * 8 + 2 * tg;
            size_t b0 = (size_t)(i0 * LL + l) * DD + h * DHH + c0;
            size_t b1 = (size_t)((i0 + 8) * LL + l) * DD + h * DHH + c0;
            float2 x0 = *(const float2*)(xin + b0);
            float2 x1v = *(const float2*)(xin + b1);
            *(float2*)(out + b0) = make_float2(x0.x + acc2[mf][nf][0],
                                               x0.y + acc2[mf][nf][1]);
            *(float2*)(out + b1) = make_float2(x1v.x + acc2[mf][nf][2],
                                               x1v.y + acc2[mf][nf][3]);
        }
    }
}

// ---------------- launch ---------------------------------------------------
extern "C" void kernel_launch(void* const* d_in, const int* in_sizes, int n_in,
                              void* d_out, int out_size)
{
    const float* x     = (const float*)d_in[0];
    const float* mask  = (const float*)d_in[1];
    const float* w_row = (const float*)d_in[2];
    const float* b_row = (const float*)d_in[3];
    const float* w_col = (const float*)d_in[4];
    const float* b_col = (const float*)d_in[5];
    const float* g1    = (const float*)d_in[6];
    const float* be1   = (const float*)d_in[7];
    const float* g2    = (const float*)d_in[8];
    const float* be2   = (const float*)d_in[9];
    float* out = (float*)d_out;

    __half *p_ah, *p_al, *p_wh, *p_wl, *p_qh, *p_ql, *p_maps16;
    float *p_x1, *p_spart, *p_rm;
    cudaGetSymbolAddress((void**)&p_ah,     g_ah);
    cudaGetSymbolAddress((void**)&p_al,     g_al);
    cudaGetSymbolAddress((void**)&p_wh,     g_wh);
    cudaGetSymbolAddress((void**)&p_wl,     g_wl);
    cudaGetSymbolAddress((void**)&p_qh,     g_qh);
    cudaGetSymbolAddress((void**)&p_ql,     g_ql);
    cudaGetSymbolAddress((void**)&p_maps16, g_maps16);
    cudaGetSymbolAddress((void**)&p_x1,     g_x1);
    cudaGetSymbolAddress((void**)&p_spart,  g_spart);
    cudaGetSymbolAddress((void**)&p_rm,     g_rm);

    cudaFuncSetAttribute(qkv_fp16,
                         cudaFuncAttributeMaxDynamicSharedMemorySize, QF_SMEMB);
    cudaFuncSetAttribute(rowscore_mma,
                         cudaFuncAttributeMaxDynamicSharedMemorySize, QF_SMEMB);
    cudaFuncSetAttribute(rowout_mma,
                         cudaFuncAttributeMaxDynamicSharedMemorySize, RO_SMEMB);
    cudaFuncSetAttribute(colfused_mma,
                         cudaFuncAttributeMaxDynamicSharedMemorySize, CF_SMEMB);

    // ---- row attention ----
    ln_split_kernel<<<RR, 256>>>(x, g1, be1, p_ah, p_al);
    wsplit_kernel<<<TD, 256>>>(w_row, p_wh, p_wl);
    qkv_fp16<<<dim3(TD / 128, RR / 128), 256, QF_SMEMB>>>(
        p_ah, p_al, p_wh, p_wl, b_row, p_qh, p_ql, 12);
    rowmask_kernel<<<HH, LL>>>(mask, p_rm);
    rowscore_mma<<<dim3(2, 2, HH * 8), 256, QF_SMEMB>>>(p_qh, p_ql, p_spart);
    rowsoftmax_kernel<<<dim3(LL, HH), LL>>>(p_spart, p_rm, p_maps16);
    rowout_mma<<<dim3(2, EE, HH), 256, RO_SMEMB>>>(p_maps16, p_qh, p_ql, x, p_x1);

    // ---- column attention ----
    ln_split_kernel<<<RR, 256>>>(p_x1, g2, be2, p_ah, p_al);
    wsplit_kernel<<<TD, 256>>>(w_col, p_wh, p_wl);
    qkv_fp16<<<dim3(TD / 128, RR / 128), 256, QF_SMEMB>>>(
        p_ah, p_al, p_wh, p_wl, b_col, p_qh, p_ql, 12);
    colfused_mma<<<dim3(LL, HH), 256, CF_SMEMB>>>(p_qh, p_ql, mask, p_x1, out);
}